// round 6
// baseline (speedup 1.0000x reference)
#include <cuda_runtime.h>
#include <cuda_bf16.h>
#include <math.h>
#include <stdint.h>

#define BATCH 2
#define CIN 256
#define COUT 256
#define HHI 256
#define WHI 512
#define HLO 128
#define WLO 256
#define MMAX 129
#define LMAX 128
#define CPG 8
#define BC (BATCH*CIN)          /* 512    */
#define ROWS1 (BC*HHI)          /* 131072 */
#define ROWS2 (BC*HLO)          /* 65536  */
#define HWLO (HLO*WLO)          /* 32768  */

// -------- scratch (static device globals; no allocation allowed) --------
__device__ __align__(16) __nv_bfloat16 d_Xr_hi[MMAX*ROWS1];
__device__ __align__(16) __nv_bfloat16 d_Xr_lo[MMAX*ROWS1];
__device__ __align__(16) __nv_bfloat16 d_Xi_hi[MMAX*ROWS1];
__device__ __align__(16) __nv_bfloat16 d_Xi_lo[MMAX*ROWS1];
__device__ __align__(16) __nv_bfloat16 d_At_hi[MMAX*HLO*HHI];   // [m][klo][kh]
__device__ __align__(16) __nv_bfloat16 d_At_lo[MMAX*HLO*HHI];
__device__ __align__(16) __nv_bfloat16 d_Whi[COUT*CIN];
__device__ __align__(16) __nv_bfloat16 d_Wlo[COUT*CIN];
__device__ float d_Gr[MMAX*ROWS2];        // [m][bc*128+klo]
__device__ float d_Gi[MMAX*ROWS2];
__device__ __align__(16) __nv_bfloat16 d_Yc_hi[BC*HWLO];  // [b][c][hw]
__device__ __align__(16) __nv_bfloat16 d_Yc_lo[BC*HWLO];
__device__ float d_H [BC*HWLO];           // [b][o][hw]
__device__ double d_ps[512], d_ps2[512];
__device__ float d_mean[BATCH*32];
__device__ float d_rstd[BATCH*32];

// ======================= helpers =======================
__device__ __forceinline__ uint32_t smem_u32(const void* p) {
    uint32_t a;
    asm("{ .reg .u64 t; cvta.to.shared.u64 t, %1; cvt.u32.u64 %0, t; }" : "=r"(a) : "l"(p));
    return a;
}
__device__ __forceinline__ void ldsm_x4(uint32_t& r0, uint32_t& r1, uint32_t& r2, uint32_t& r3, uint32_t addr) {
    asm volatile("ldmatrix.sync.aligned.m8n8.x4.shared.b16 {%0,%1,%2,%3}, [%4];"
        : "=r"(r0), "=r"(r1), "=r"(r2), "=r"(r3) : "r"(addr));
}
__device__ __forceinline__ void ldsm_x4_t(uint32_t& r0, uint32_t& r1, uint32_t& r2, uint32_t& r3, uint32_t addr) {
    asm volatile("ldmatrix.sync.aligned.m8n8.x4.trans.shared.b16 {%0,%1,%2,%3}, [%4];"
        : "=r"(r0), "=r"(r1), "=r"(r2), "=r"(r3) : "r"(addr));
}
__device__ __forceinline__ void mma16816(float* d, const uint32_t* a, uint32_t b0, uint32_t b1) {
    asm volatile("mma.sync.aligned.m16n8k16.row.col.f32.bf16.bf16.f32 "
        "{%0,%1,%2,%3}, {%4,%5,%6,%7}, {%8,%9}, {%0,%1,%2,%3};"
        : "+f"(d[0]), "+f"(d[1]), "+f"(d[2]), "+f"(d[3])
        : "r"(a[0]), "r"(a[1]), "r"(a[2]), "r"(a[3]), "r"(b0), "r"(b1));
}
__device__ __forceinline__ void cp16(uint32_t dst, const void* src) {
    asm volatile("cp.async.cg.shared.global [%0], [%1], 16;" :: "r"(dst), "l"(src));
}
#define CP_COMMIT() asm volatile("cp.async.commit_group;" ::: "memory")
__device__ __forceinline__ void split2(float v, __nv_bfloat16& h, __nv_bfloat16& l) {
    h = __float2bfloat16(v);
    l = __float2bfloat16(v - __bfloat162float(h));
}

// stage layout: Ahi(8K) Alo(8K) Bhi(8K) Blo(8K) = 32KB; 3 stages = 96KB
#define STG (32768)
#define GEMM_SMEM (3*STG)

// non-trans tile [128 rows][32 k], 64B rows, swizzle c^((row>>1)&3)
#define OFF_NT(row, c) ((uint32_t)((row)<<6) + (uint32_t)(((c) ^ (((row)>>1)&3)) << 4))
// trans tile [32 k][128 n], 256B rows, swizzle c^(k&7)
#define OFF_T(k, c16)  ((uint32_t)((k)<<8) + (uint32_t)(((c16) ^ ((k)&7)) << 4))

// ============================================================
// GEMM core, both operands k-major: D[128m][128n] = A[128][256] B[128][256]^T
// 3-stage cp.async, K-chunks of 32, 3-term bf16 split.
// ============================================================
__device__ __forceinline__ void gemm_nn(
    const __nv_bfloat16* __restrict__ Ahi, const __nv_bfloat16* __restrict__ Alo,
    const __nv_bfloat16* __restrict__ Bhi, const __nv_bfloat16* __restrict__ Blo,
    float* __restrict__ D, int ldD, const float* __restrict__ bias, uint32_t sm)
{
    int tid = threadIdx.x;
    int wid = tid >> 5, lane = tid & 31;
    int wm = wid >> 1, wn = wid & 1;

    float acc[2][8][4];
    #pragma unroll
    for (int i=0;i<2;i++) for (int j=0;j<8;j++) for (int q=0;q<4;q++) acc[i][j][q] = 0.f;

    auto load_chunk = [&](int kc) {
        uint32_t base = sm + (kc % 3)*STG;
        #pragma unroll
        for (int e = tid; e < 512; e += 256) {
            int row = e >> 2, c = e & 3;
            uint32_t off = OFF_NT(row, c);
            size_t g = (size_t)row*256 + kc*32 + c*8;
            cp16(base          + off, Ahi + g);
            cp16(base +  8192  + off, Alo + g);
            cp16(base + 16384  + off, Bhi + g);
            cp16(base + 24576  + off, Blo + g);
        }
        CP_COMMIT();
    };

    load_chunk(0); load_chunk(1); load_chunk(2);

    #pragma unroll 1
    for (int kc = 0; kc < 8; kc++) {
        if (kc < 6)      asm volatile("cp.async.wait_group 2;" ::: "memory");
        else if (kc == 6) asm volatile("cp.async.wait_group 1;" ::: "memory");
        else             asm volatile("cp.async.wait_group 0;" ::: "memory");
        __syncthreads();

        uint32_t base = sm + (kc % 3)*STG;
        uint32_t sAhi = base, sAlo = base + 8192, sBhi = base + 16384, sBlo = base + 24576;

        #pragma unroll
        for (int ks = 0; ks < 2; ks++) {
            int c = ks*2 + (lane >> 4);
            uint32_t a_h[2][4], a_l[2][4];
            #pragma unroll
            for (int mi = 0; mi < 2; mi++) {
                int row = wm*32 + mi*16 + (lane & 15);
                uint32_t off = OFF_NT(row, c);
                ldsm_x4(a_h[mi][0], a_h[mi][1], a_h[mi][2], a_h[mi][3], sAhi + off);
                ldsm_x4(a_l[mi][0], a_l[mi][1], a_l[mi][2], a_l[mi][3], sAlo + off);
            }
            uint32_t b[4][4];
            #pragma unroll
            for (int nj = 0; nj < 4; nj++) {
                int row = wn*64 + nj*16 + (lane & 7) + ((lane >> 3) & 1)*8;
                uint32_t off = OFF_NT(row, c);
                ldsm_x4(b[nj][0], b[nj][1], b[nj][2], b[nj][3], sBhi + off);
            }
            #pragma unroll
            for (int mi = 0; mi < 2; mi++)
                #pragma unroll
                for (int nj = 0; nj < 4; nj++) {
                    mma16816(acc[mi][nj*2],   a_h[mi], b[nj][0], b[nj][2]);
                    mma16816(acc[mi][nj*2+1], a_h[mi], b[nj][1], b[nj][3]);
                }
            #pragma unroll
            for (int mi = 0; mi < 2; mi++)
                #pragma unroll
                for (int nj = 0; nj < 4; nj++) {
                    mma16816(acc[mi][nj*2],   a_l[mi], b[nj][0], b[nj][2]);
                    mma16816(acc[mi][nj*2+1], a_l[mi], b[nj][1], b[nj][3]);
                }
            #pragma unroll
            for (int nj = 0; nj < 4; nj++) {
                int row = wn*64 + nj*16 + (lane & 7) + ((lane >> 3) & 1)*8;
                uint32_t off = OFF_NT(row, c);
                ldsm_x4(b[nj][0], b[nj][1], b[nj][2], b[nj][3], sBlo + off);
            }
            #pragma unroll
            for (int mi = 0; mi < 2; mi++)
                #pragma unroll
                for (int nj = 0; nj < 4; nj++) {
                    mma16816(acc[mi][nj*2],   a_h[mi], b[nj][0], b[nj][2]);
                    mma16816(acc[mi][nj*2+1], a_h[mi], b[nj][1], b[nj][3]);
                }
        }
        __syncthreads();
        if (kc + 3 < 8) load_chunk(kc + 3);
    }

    int g = lane >> 2, tg = lane & 3;
    #pragma unroll
    for (int mi = 0; mi < 2; mi++) {
        int r0 = wm*32 + mi*16 + g;
        float bv0 = bias ? bias[r0]   : 0.f;
        float bv1 = bias ? bias[r0+8] : 0.f;
        #pragma unroll
        for (int nt = 0; nt < 8; nt++) {
            int col = wn*64 + nt*8 + tg*2;
            float2 v0 = make_float2(acc[mi][nt][0] + bv0, acc[mi][nt][1] + bv0);
            float2 v1 = make_float2(acc[mi][nt][2] + bv1, acc[mi][nt][3] + bv1);
            *(float2*)&D[(size_t)r0*ldD + col]     = v0;
            *(float2*)&D[(size_t)(r0+8)*ldD + col] = v1;
        }
    }
}

// ============================================================
// GEMM core, A k-major [128 m][256 k], B row-major [256 k][N] (ldB stride):
// D[128m][128n] = sum_k A[m][k] B[k][n]. B loaded via ldmatrix.trans.
// ============================================================
__device__ __forceinline__ void gemm_kn(
    const __nv_bfloat16* __restrict__ Ahi, const __nv_bfloat16* __restrict__ Alo,
    const __nv_bfloat16* __restrict__ Bhi, const __nv_bfloat16* __restrict__ Blo,
    size_t ldB,
    float* __restrict__ D, int ldD, const float* __restrict__ bias, uint32_t sm)
{
    int tid = threadIdx.x;
    int wid = tid >> 5, lane = tid & 31;
    int wm = wid >> 1, wn = wid & 1;

    float acc[2][8][4];
    #pragma unroll
    for (int i=0;i<2;i++) for (int j=0;j<8;j++) for (int q=0;q<4;q++) acc[i][j][q] = 0.f;

    auto load_chunk = [&](int kc) {
        uint32_t base = sm + (kc % 3)*STG;
        #pragma unroll
        for (int e = tid; e < 512; e += 256) {
            int row = e >> 2, c = e & 3;
            uint32_t off = OFF_NT(row, c);
            size_t gA = (size_t)row*256 + kc*32 + c*8;
            cp16(base         + off, Ahi + gA);
            cp16(base +  8192 + off, Alo + gA);
            int kr = e >> 4, c16 = e & 15;              // B: 32 k-rows x 16 chunks
            uint32_t offb = OFF_T(kr, c16);
            size_t gB = (size_t)(kc*32 + kr)*ldB + c16*8;
            cp16(base + 16384 + offb, Bhi + gB);
            cp16(base + 24576 + offb, Blo + gB);
        }
        CP_COMMIT();
    };

    load_chunk(0); load_chunk(1); load_chunk(2);

    #pragma unroll 1
    for (int kc = 0; kc < 8; kc++) {
        if (kc < 6)      asm volatile("cp.async.wait_group 2;" ::: "memory");
        else if (kc == 6) asm volatile("cp.async.wait_group 1;" ::: "memory");
        else             asm volatile("cp.async.wait_group 0;" ::: "memory");
        __syncthreads();

        uint32_t base = sm + (kc % 3)*STG;
        uint32_t sAhi = base, sAlo = base + 8192, sBhi = base + 16384, sBlo = base + 24576;

        #pragma unroll
        for (int ks = 0; ks < 2; ks++) {
            int c = ks*2 + (lane >> 4);
            uint32_t a_h[2][4], a_l[2][4];
            #pragma unroll
            for (int mi = 0; mi < 2; mi++) {
                int row = wm*32 + mi*16 + (lane & 15);
                uint32_t off = OFF_NT(row, c);
                ldsm_x4(a_h[mi][0], a_h[mi][1], a_h[mi][2], a_h[mi][3], sAhi + off);
                ldsm_x4(a_l[mi][0], a_l[mi][1], a_l[mi][2], a_l[mi][3], sAlo + off);
            }
            // trans-B: k = ks*16 + (lane&7) + ((lane>>3)&1)*8 ; n = nj*16 + ((lane>>4)&1)*8
            int kr = ks*16 + (lane & 7) + ((lane >> 3) & 1)*8;
            uint32_t b[4][4];
            #pragma unroll
            for (int nj = 0; nj < 4; nj++) {
                int n = wn*64 + nj*16 + ((lane >> 4) & 1)*8;
                uint32_t off = OFF_T(kr, (n >> 3));
                ldsm_x4_t(b[nj][0], b[nj][1], b[nj][2], b[nj][3], sBhi + off);
            }
            #pragma unroll
            for (int mi = 0; mi < 2; mi++)
                #pragma unroll
                for (int nj = 0; nj < 4; nj++) {
                    mma16816(acc[mi][nj*2],   a_h[mi], b[nj][0], b[nj][1]);
                    mma16816(acc[mi][nj*2+1], a_h[mi], b[nj][2], b[nj][3]);
                }
            #pragma unroll
            for (int mi = 0; mi < 2; mi++)
                #pragma unroll
                for (int nj = 0; nj < 4; nj++) {
                    mma16816(acc[mi][nj*2],   a_l[mi], b[nj][0], b[nj][1]);
                    mma16816(acc[mi][nj*2+1], a_l[mi], b[nj][2], b[nj][3]);
                }
            #pragma unroll
            for (int nj = 0; nj < 4; nj++) {
                int n = wn*64 + nj*16 + ((lane >> 4) & 1)*8;
                uint32_t off = OFF_T(kr, (n >> 3));
                ldsm_x4_t(b[nj][0], b[nj][1], b[nj][2], b[nj][3], sBlo + off);
            }
            #pragma unroll
            for (int mi = 0; mi < 2; mi++)
                #pragma unroll
                for (int nj = 0; nj < 4; nj++) {
                    mma16816(acc[mi][nj*2],   a_h[mi], b[nj][0], b[nj][1]);
                    mma16816(acc[mi][nj*2+1], a_h[mi], b[nj][2], b[nj][3]);
                }
        }
        __syncthreads();
        if (kc + 3 < 8) load_chunk(kc + 3);
    }

    int g = lane >> 2, tg = lane & 3;
    #pragma unroll
    for (int mi = 0; mi < 2; mi++) {
        int r0 = wm*32 + mi*16 + g;
        float bv0 = bias ? bias[r0]   : 0.f;
        float bv1 = bias ? bias[r0+8] : 0.f;
        #pragma unroll
        for (int nt = 0; nt < 8; nt++) {
            int col = wn*64 + nt*8 + tg*2;
            float2 v0 = make_float2(acc[mi][nt][0] + bv0, acc[mi][nt][1] + bv0);
            float2 v1 = make_float2(acc[mi][nt][2] + bv1, acc[mi][nt][3] + bv1);
            *(float2*)&D[(size_t)r0*ldD + col]     = v0;
            *(float2*)&D[(size_t)(r0+8)*ldD + col] = v1;
        }
    }
}

// ============================================================
// Stage 1: rfft(512) per row, scaled by 2*pi/512. Output bf16 hi/lo, [m][row].
// 1024 threads, 32 rows/block -> 64B transposed store runs.
// ============================================================
#define FFT_SMEM (32*256*2*4)
__global__ void __launch_bounds__(1024) k_fft_fwd(const float* __restrict__ x) {
    extern __shared__ float fsm[];
    float* sre = fsm;            // [32][256]
    float* sim = fsm + 32*256;
    __shared__ float twr[128], twi[128];
    __shared__ float uer[129], uei[129];
    int tid = threadIdx.x;
    if (tid < 128) { float s,c; sincosf(-6.283185307179586f*(float)tid/256.0f,&s,&c); twr[tid]=c; twi[tid]=s; }
    if (tid < 129) { float s,c; sincosf(-6.283185307179586f*(float)tid/512.0f,&s,&c); uer[tid]=c; uei[tid]=s; }
    __syncthreads();
    int w = tid >> 5, lane = tid & 31;
    float* re = sre + w*256;
    float* im = sim + w*256;
    int row = blockIdx.x*32 + w;
    const float4* xr4 = (const float4*)(x + (size_t)row*512);
    #pragma unroll
    for (int j = 0; j < 4; j++) {
        float4 v = xr4[lane + 32*j];
        int f  = lane + 32*j;
        int r0 = __brev(2*f)   >> 24;
        int r1 = __brev(2*f+1) >> 24;
        re[r0]=v.x; im[r0]=v.y;
        re[r1]=v.z; im[r1]=v.w;
    }
    __syncwarp();
    for (int st = 0; st < 8; st++) {
        int half = 1 << st;
        int tstep = 128 >> st;
        #pragma unroll 4
        for (int b = lane; b < 128; b += 32) {
            int blk = b >> st;
            int j   = b & (half-1);
            int i0  = (blk << (st+1)) + j;
            int i1  = i0 + half;
            float wr = twr[j*tstep], wi = twi[j*tstep];
            float ur = re[i0], ui = im[i0];
            float vr = re[i1], vi = im[i1];
            float tr = vr*wr - vi*wi, ti = vr*wi + vi*wr;
            re[i0]=ur+tr; im[i0]=ui+ti;
            re[i1]=ur-tr; im[i1]=ui-ti;
        }
        __syncwarp();
    }
    const float SC = 0.012271846303085129f;  // 2*pi/512
    float ro[5], io[5];
    #pragma unroll
    for (int j = 0; j < 5; j++) {
        int k = lane + 32*j;
        if (k <= 128) {
            int km = (256-k) & 255;
            float zr=re[k],  zi= im[k];
            float mr=re[km], mi=-im[km];
            float er=0.5f*(zr+mr), ei=0.5f*(zi+mi);
            float dr=0.5f*(zr-mr), di=0.5f*(zi-mi);
            float pr=di, pi=-dr;
            float wr=uer[k], wi=uei[k];
            float qr=pr*wr-pi*wi, qi=pr*wi+pi*wr;
            ro[j] = (er+qr)*SC;
            io[j] = (ei+qi)*SC;
        }
    }
    __syncthreads();
    float* ore = sre;   // reuse: [129][32]
    float* oim = sim;
    #pragma unroll
    for (int j = 0; j < 5; j++) {
        int k = lane + 32*j;
        if (k <= 128) { ore[k*32+w] = ro[j]; oim[k*32+w] = io[j]; }
    }
    __syncthreads();
    int base = blockIdx.x*32;
    for (int idx = tid; idx < 129*32; idx += 1024) {
        int m = idx >> 5, r = idx & 31;
        size_t o = (size_t)m*ROWS1 + base + r;
        __nv_bfloat16 h, l;
        split2(ore[idx], h, l); d_Xr_hi[o]=h; d_Xr_lo[o]=l;
        split2(oim[idx], h, l); d_Xi_hi[o]=h; d_Xi_lo[o]=l;
    }
}

// ============================================================
// Stage 2: At[m][klo][kh] = sum_l wmat[m][l][kh]*pct[m][l][klo], bf16 hi/lo.
// ============================================================
__global__ void k_buildA(const float* __restrict__ wmat, const float* __restrict__ pct) {
    int m    = blockIdx.z;
    int kh0  = blockIdx.x * 64;
    int klo0 = blockIdx.y * 64;
    __shared__ float sW[16][65];
    __shared__ float sP[16][64];
    int tid = threadIdx.x;
    int tx = tid & 15, ty = tid >> 4;
    float acc[4][4] = {};
    const float* wbase = wmat + m*LMAX*HHI;
    const float* pbase = pct  + m*LMAX*HLO;
    for (int l0 = 0; l0 < 128; l0 += 16) {
        #pragma unroll
        for (int q = 0; q < 4; q++) {
            int e = tid + q*256;
            int li = e >> 6, ki = e & 63;
            sW[li][ki] = wbase[(l0+li)*HHI + kh0  + ki];
            sP[li][ki] = pbase[(l0+li)*HLO + klo0 + ki];
        }
        __syncthreads();
        #pragma unroll
        for (int l = 0; l < 16; l++) {
            float a[4], b[4];
            #pragma unroll
            for (int i=0;i<4;i++) a[i]=sW[l][ty*4+i];
            #pragma unroll
            for (int j=0;j<4;j++) b[j]=sP[l][tx*4+j];
            #pragma unroll
            for (int i=0;i<4;i++)
                #pragma unroll
                for (int j=0;j<4;j++) acc[i][j] += a[i]*b[j];
        }
        __syncthreads();
    }
    size_t Abase = (size_t)m*(HLO*HHI);
    #pragma unroll
    for (int j=0;j<4;j++) {
        int klo = klo0 + tx*4 + j;
        __nv_bfloat162 ph0, ph1, pl0, pl1;
        __nv_bfloat16 h, l;
        split2(acc[0][j], h, l); ph0.x=h; pl0.x=l;
        split2(acc[1][j], h, l); ph0.y=h; pl0.y=l;
        split2(acc[2][j], h, l); ph1.x=h; pl1.x=l;
        split2(acc[3][j], h, l); ph1.y=h; pl1.y=l;
        size_t o = Abase + (size_t)klo*HHI + kh0 + ty*4;
        *(__nv_bfloat162*)&d_At_hi[o]   = ph0;
        *(__nv_bfloat162*)&d_At_hi[o+2] = ph1;
        *(__nv_bfloat162*)&d_At_lo[o]   = pl0;
        *(__nv_bfloat162*)&d_At_lo[o+2] = pl1;
    }
}

// ============================================================
// Stage 2b: split conv weights to bf16 hi/lo
// ============================================================
__global__ void k_wsplit(const float* __restrict__ w) {
    int i = blockIdx.x*256 + threadIdx.x;   // 65536 total
    __nv_bfloat16 h, l;
    split2(w[i], h, l);
    d_Whi[i] = h; d_Wlo[i] = l;
}

// ============================================================
// Stage 3: Legendre per-m GEMM.
// blockIdx.x 0..7: [0..3]=real bc-tiles, [4..7]=imag. blockIdx.y = m.
// ============================================================
__global__ void __launch_bounds__(256) k_legendre_mma() {
    extern __shared__ __align__(128) char dsm[];
    int m = blockIdx.y;
    int bx = blockIdx.x;
    int half = bx >> 2;
    int bc0  = (bx & 3) * 128;
    size_t xo = (size_t)m*ROWS1 + (size_t)bc0*HHI;
    const __nv_bfloat16 *Ah, *Al;
    float* D;
    if (half) { Ah = d_Xi_hi + xo; Al = d_Xi_lo + xo; D = d_Gi; }
    else      { Ah = d_Xr_hi + xo; Al = d_Xr_lo + xo; D = d_Gr; }
    D += (size_t)m*ROWS2 + (size_t)bc0*HLO;
    const __nv_bfloat16* Bh = d_At_hi + (size_t)m*(HLO*HHI);
    const __nv_bfloat16* Bl = d_At_lo + (size_t)m*(HLO*HHI);
    gemm_nn(Ah, Al, Bh, Bl, D, HLO, nullptr, smem_u32(dsm));
}

// ============================================================
// Stage 4: irfft(n=256)*256 per row. Output directly bf16 hi/lo [b][c][hw].
// ============================================================
__global__ void k_ifft() {
    __shared__ float gre[129*8], gim[129*8];
    __shared__ float sre[8][128], sim[8][128];
    __shared__ float wqr[128], wqi[128];
    __shared__ float t2r[64],  t2i[64];
    int tid = threadIdx.x;
    if (tid < 128){ float s,c; sincosf(6.283185307179586f*(float)tid/256.f,&s,&c); wqr[tid]=c; wqi[tid]=s; }
    if (tid < 64 ){ float s,c; sincosf(6.283185307179586f*(float)tid/128.f,&s,&c); t2r[tid]=c; t2i[tid]=s; }
    int base = blockIdx.x*8;
    for (int idx = tid; idx < 129*8; idx += 256) {
        int m = idx >> 3, r = idx & 7;
        gre[idx] = d_Gr[m*ROWS2 + base + r];
        gim[idx] = d_Gi[m*ROWS2 + base + r];
    }
    __syncthreads();
    int w = tid >> 5, lane = tid & 31;
    #pragma unroll 4
    for (int k = lane; k < 128; k += 32) {
        float ar = gre[k*8+w],        ai =  gim[k*8+w];
        float br = gre[(128-k)*8+w],  bi = -gim[(128-k)*8+w];
        float wr = wqr[k], wi = wqi[k];
        float c1r = 1.f - wi, c1i =  wr;
        float c2r = 1.f + wi, c2i = -wr;
        float Zr = ar*c1r - ai*c1i + br*c2r - bi*c2i;
        float Zi = ar*c1i + ai*c1r + br*c2i + bi*c2r;
        int rv = __brev(k) >> 25;
        sre[w][rv] = Zr; sim[w][rv] = Zi;
    }
    __syncwarp();
    for (int st = 0; st < 7; st++) {
        int half = 1 << st;
        int tstep = 64 >> st;
        #pragma unroll 2
        for (int b = lane; b < 64; b += 32) {
            int blk = b >> st;
            int j   = b & (half-1);
            int i0  = (blk << (st+1)) + j;
            int i1  = i0 + half;
            float wr = t2r[j*tstep], wi = t2i[j*tstep];
            float ur = sre[w][i0], ui = sim[w][i0];
            float vr = sre[w][i1], vi = sim[w][i1];
            float tr = vr*wr - vi*wi, ti = vr*wi + vi*wr;
            sre[w][i0]=ur+tr; sim[w][i0]=ui+ti;
            sre[w][i1]=ur-tr; sim[w][i1]=ui-ti;
        }
        __syncwarp();
    }
    // y[2n] = Re z[n], y[2n+1] = Im z[n]; store bf16 hi/lo pairs
    __nv_bfloat162* yh = (__nv_bfloat162*)d_Yc_hi + (size_t)(base + w)*128;
    __nv_bfloat162* yl = (__nv_bfloat162*)d_Yc_lo + (size_t)(base + w)*128;
    #pragma unroll 4
    for (int n = lane; n < 128; n += 32) {
        __nv_bfloat16 h0,l0,h1,l1;
        split2(sre[w][n], h0, l0);
        split2(sim[w][n], h1, l1);
        __nv_bfloat162 vh; vh.x=h0; vh.y=h1;
        __nv_bfloat162 vl; vl.x=l0; vl.y=l1;
        yh[n] = vh; yl[n] = vl;
    }
}

// ============================================================
// Stage 5: 1x1 conv. D[o][hw] = W[o][c] * Y[c][hw]  (B consumed via ldmatrix.trans)
// ============================================================
__global__ void __launch_bounds__(256) k_conv_mma(const float* __restrict__ bias) {
    extern __shared__ __align__(128) char dsm[];
    int b = blockIdx.z, o0 = blockIdx.y*128, hw0 = blockIdx.x*128;
    const __nv_bfloat16* Ah = d_Whi + (size_t)o0*CIN;
    const __nv_bfloat16* Al = d_Wlo + (size_t)o0*CIN;
    const __nv_bfloat16* Bh = d_Yc_hi + (size_t)b*CIN*HWLO + hw0;
    const __nv_bfloat16* Bl = d_Yc_lo + (size_t)b*CIN*HWLO + hw0;
    float* D = d_H + ((size_t)b*COUT + o0)*HWLO + hw0;
    gemm_kn(Ah, Al, Bh, Bl, (size_t)HWLO, D, HWLO, bias + o0, smem_u32(dsm));
}

// ============================================================
// Stage 6: GroupNorm stats — two-phase deterministic reduction.
// ============================================================
__global__ void k_gnstat1() {
    int blk = blockIdx.x;             // 512 = 64 groups * 8 parts
    int bg = blk >> 3, part = blk & 7;
    const float* hb = d_H + (size_t)bg*(CPG*HWLO) + part*32768;
    double s = 0.0, s2 = 0.0;
    for (int i = threadIdx.x; i < 32768; i += 256) {
        float v = hb[i];
        s += (double)v; s2 += (double)v*(double)v;
    }
    __shared__ double sh[256], sh2[256];
    sh[threadIdx.x] = s; sh2[threadIdx.x] = s2;
    __syncthreads();
    for (int st = 128; st > 0; st >>= 1) {
        if (threadIdx.x < st) { sh[threadIdx.x] += sh[threadIdx.x+st]; sh2[threadIdx.x] += sh2[threadIdx.x+st]; }
        __syncthreads();
    }
    if (threadIdx.x == 0) { d_ps[blk] = sh[0]; d_ps2[blk] = sh2[0]; }
}
__global__ void k_gnstat2() {
    int bg = threadIdx.x;             // 64 threads
    double s = 0.0, s2 = 0.0;
    #pragma unroll
    for (int p = 0; p < 8; p++) { s += d_ps[bg*8+p]; s2 += d_ps2[bg*8+p]; }
    const double N = (double)(CPG*HWLO);
    double mean = s / N;
    double var  = s2 / N - mean*mean;
    d_mean[bg] = (float)mean;
    d_rstd[bg] = rsqrtf((float)var + 1e-5f);
}

// ============================================================
// Stage 7: normalize + affine + exact GELU
// ============================================================
__global__ void k_gnapply(const float* __restrict__ gamma, const float* __restrict__ beta,
                          float* __restrict__ out) {
    int idx = blockIdx.x*256 + threadIdx.x;
    int fidx = idx * 4;
    int o  = (fidx >> 15) & 255;
    int bg = fidx >> 18;
    float a  = gamma[o] * d_rstd[bg];
    float b2 = beta[o] - d_mean[bg] * a;
    float4 h = ((const float4*)d_H)[idx];
    float v0 = h.x*a + b2, v1 = h.y*a + b2, v2 = h.z*a + b2, v3 = h.w*a + b2;
    float4 r;
    r.x = v0 * normcdff(v0);
    r.y = v1 * normcdff(v1);
    r.z = v2 * normcdff(v2);
    r.w = v3 * normcdff(v3);
    ((float4*)out)[idx] = r;
}

// ============================================================
extern "C" void kernel_launch(void* const* d_in, const int* in_sizes, int n_in,
                              void* d_out, int out_size) {
    const float* x      = (const float*)d_in[0];
    const float* conv_w = (const float*)d_in[1];
    const float* conv_b = (const float*)d_in[2];
    const float* gamma  = (const float*)d_in[3];
    const float* beta   = (const float*)d_in[4];
    const float* wmat   = (const float*)d_in[5];
    const float* pct    = (const float*)d_in[6];
    float* out = (float*)d_out;

    cudaFuncSetAttribute(k_fft_fwd,      cudaFuncAttributeMaxDynamicSharedMemorySize, FFT_SMEM);
    cudaFuncSetAttribute(k_legendre_mma, cudaFuncAttributeMaxDynamicSharedMemorySize, GEMM_SMEM);
    cudaFuncSetAttribute(k_conv_mma,     cudaFuncAttributeMaxDynamicSharedMemorySize, GEMM_SMEM);

    k_fft_fwd     <<<ROWS1/32, 1024, FFT_SMEM>>>(x);
    k_buildA      <<<dim3(4,2,MMAX), 256>>>(wmat, pct);
    k_wsplit      <<<256, 256>>>(conv_w);
    k_legendre_mma<<<dim3(8, MMAX), 256, GEMM_SMEM>>>();
    k_ifft        <<<ROWS2/8, 256>>>();
    k_conv_mma    <<<dim3(HWLO/128, COUT/128, BATCH), 256, GEMM_SMEM>>>(conv_b);
    k_gnstat1     <<<512, 256>>>();
    k_gnstat2     <<<1, 64>>>();
    k_gnapply     <<<(BC*HWLO)/4/256, 256>>>(gamma, beta, out);
}

// round 7
// speedup vs baseline: 1.3536x; 1.3536x over previous
#include <cuda_runtime.h>
#include <cuda_bf16.h>
#include <math.h>
#include <stdint.h>

#define BATCH 2
#define CIN 256
#define COUT 256
#define HHI 256
#define WHI 512
#define HLO 128
#define WLO 256
#define MMAX 129
#define LMAX 128
#define CPG 8
#define BC (BATCH*CIN)          /* 512    */
#define ROWS1 (BC*HHI)          /* 131072 */
#define ROWS2 (BC*HLO)          /* 65536  */
#define HWLO (HLO*WLO)          /* 32768  */

// -------- scratch (static device globals; no allocation allowed) --------
__device__ __align__(16) __nv_bfloat16 d_Xr_hi[MMAX*ROWS1];
__device__ __align__(16) __nv_bfloat16 d_Xr_lo[MMAX*ROWS1];
__device__ __align__(16) __nv_bfloat16 d_Xi_hi[MMAX*ROWS1];
__device__ __align__(16) __nv_bfloat16 d_Xi_lo[MMAX*ROWS1];
__device__ __align__(16) __nv_bfloat16 d_At_hi[MMAX*HLO*HHI];   // [m][klo][kh]
__device__ __align__(16) __nv_bfloat16 d_At_lo[MMAX*HLO*HHI];
__device__ __align__(16) __nv_bfloat16 d_Whi[COUT*CIN];
__device__ __align__(16) __nv_bfloat16 d_Wlo[COUT*CIN];
__device__ float d_Gr[MMAX*ROWS2];        // [m][bc*128+klo]
__device__ float d_Gi[MMAX*ROWS2];
__device__ __align__(16) __nv_bfloat16 d_Yc_hi[BC*HWLO];  // [b][c][hw]
__device__ __align__(16) __nv_bfloat16 d_Yc_lo[BC*HWLO];
__device__ float d_H [BC*HWLO];           // [b][o][hw]
__device__ double d_ps[512], d_ps2[512];
__device__ float d_mean[BATCH*32];
__device__ float d_rstd[BATCH*32];

// ======================= helpers =======================
__device__ __forceinline__ uint32_t smem_u32(const void* p) {
    uint32_t a;
    asm("{ .reg .u64 t; cvta.to.shared.u64 t, %1; cvt.u32.u64 %0, t; }" : "=r"(a) : "l"(p));
    return a;
}
__device__ __forceinline__ void ldsm_x4(uint32_t& r0, uint32_t& r1, uint32_t& r2, uint32_t& r3, uint32_t addr) {
    asm volatile("ldmatrix.sync.aligned.m8n8.x4.shared.b16 {%0,%1,%2,%3}, [%4];"
        : "=r"(r0), "=r"(r1), "=r"(r2), "=r"(r3) : "r"(addr));
}
__device__ __forceinline__ void ldsm_x4_t(uint32_t& r0, uint32_t& r1, uint32_t& r2, uint32_t& r3, uint32_t addr) {
    asm volatile("ldmatrix.sync.aligned.m8n8.x4.trans.shared.b16 {%0,%1,%2,%3}, [%4];"
        : "=r"(r0), "=r"(r1), "=r"(r2), "=r"(r3) : "r"(addr));
}
__device__ __forceinline__ void mma16816(float* d, const uint32_t* a, uint32_t b0, uint32_t b1) {
    asm volatile("mma.sync.aligned.m16n8k16.row.col.f32.bf16.bf16.f32 "
        "{%0,%1,%2,%3}, {%4,%5,%6,%7}, {%8,%9}, {%0,%1,%2,%3};"
        : "+f"(d[0]), "+f"(d[1]), "+f"(d[2]), "+f"(d[3])
        : "r"(a[0]), "r"(a[1]), "r"(a[2]), "r"(a[3]), "r"(b0), "r"(b1));
}
__device__ __forceinline__ void cp16(uint32_t dst, const void* src) {
    asm volatile("cp.async.cg.shared.global [%0], [%1], 16;" :: "r"(dst), "l"(src));
}
#define CP_COMMIT() asm volatile("cp.async.commit_group;" ::: "memory")
__device__ __forceinline__ void split2(float v, __nv_bfloat16& h, __nv_bfloat16& l) {
    h = __float2bfloat16(v);
    l = __float2bfloat16(v - __bfloat162float(h));
}

// stage layout: Ahi(8K) Alo(8K) Bhi(8K) Blo(8K) = 32KB; 3 stages = 96KB
#define STG (32768)
#define GEMM_SMEM (3*STG)

// non-trans tile [128 rows][32 k], 64B rows, swizzle c^((row>>1)&3)
#define OFF_NT(row, c) ((uint32_t)((row)<<6) + (uint32_t)(((c) ^ (((row)>>1)&3)) << 4))
// trans tile [32 k][128 n], 256B rows, swizzle c^(k&7)
#define OFF_T(k, c16)  ((uint32_t)((k)<<8) + (uint32_t)(((c16) ^ ((k)&7)) << 4))

// smem FFT pad: conflict-avoiding, float4-alignment-preserving
#define SWF(i) ((i) + ((((i)>>5))<<2))

// ============================================================
// GEMM core, both operands k-major: D[128m][128n] = A[128][256] B[128][256]^T
// ============================================================
__device__ __forceinline__ void gemm_nn(
    const __nv_bfloat16* __restrict__ Ahi, const __nv_bfloat16* __restrict__ Alo,
    const __nv_bfloat16* __restrict__ Bhi, const __nv_bfloat16* __restrict__ Blo,
    float* __restrict__ D, int ldD, const float* __restrict__ bias, uint32_t sm)
{
    int tid = threadIdx.x;
    int wid = tid >> 5, lane = tid & 31;
    int wm = wid >> 1, wn = wid & 1;

    float acc[2][8][4];
    #pragma unroll
    for (int i=0;i<2;i++) for (int j=0;j<8;j++) for (int q=0;q<4;q++) acc[i][j][q] = 0.f;

    auto load_chunk = [&](int kc) {
        uint32_t base = sm + (kc % 3)*STG;
        #pragma unroll
        for (int e = tid; e < 512; e += 256) {
            int row = e >> 2, c = e & 3;
            uint32_t off = OFF_NT(row, c);
            size_t g = (size_t)row*256 + kc*32 + c*8;
            cp16(base          + off, Ahi + g);
            cp16(base +  8192  + off, Alo + g);
            cp16(base + 16384  + off, Bhi + g);
            cp16(base + 24576  + off, Blo + g);
        }
        CP_COMMIT();
    };

    load_chunk(0); load_chunk(1); load_chunk(2);

    #pragma unroll 1
    for (int kc = 0; kc < 8; kc++) {
        if (kc < 6)      asm volatile("cp.async.wait_group 2;" ::: "memory");
        else if (kc == 6) asm volatile("cp.async.wait_group 1;" ::: "memory");
        else             asm volatile("cp.async.wait_group 0;" ::: "memory");
        __syncthreads();

        uint32_t base = sm + (kc % 3)*STG;
        uint32_t sAhi = base, sAlo = base + 8192, sBhi = base + 16384, sBlo = base + 24576;

        #pragma unroll
        for (int ks = 0; ks < 2; ks++) {
            int c = ks*2 + (lane >> 4);
            uint32_t a_h[2][4], a_l[2][4];
            #pragma unroll
            for (int mi = 0; mi < 2; mi++) {
                int row = wm*32 + mi*16 + (lane & 15);
                uint32_t off = OFF_NT(row, c);
                ldsm_x4(a_h[mi][0], a_h[mi][1], a_h[mi][2], a_h[mi][3], sAhi + off);
                ldsm_x4(a_l[mi][0], a_l[mi][1], a_l[mi][2], a_l[mi][3], sAlo + off);
            }
            uint32_t b[4][4];
            #pragma unroll
            for (int nj = 0; nj < 4; nj++) {
                int row = wn*64 + nj*16 + (lane & 7) + ((lane >> 3) & 1)*8;
                uint32_t off = OFF_NT(row, c);
                ldsm_x4(b[nj][0], b[nj][1], b[nj][2], b[nj][3], sBhi + off);
            }
            #pragma unroll
            for (int mi = 0; mi < 2; mi++)
                #pragma unroll
                for (int nj = 0; nj < 4; nj++) {
                    mma16816(acc[mi][nj*2],   a_h[mi], b[nj][0], b[nj][2]);
                    mma16816(acc[mi][nj*2+1], a_h[mi], b[nj][1], b[nj][3]);
                }
            #pragma unroll
            for (int mi = 0; mi < 2; mi++)
                #pragma unroll
                for (int nj = 0; nj < 4; nj++) {
                    mma16816(acc[mi][nj*2],   a_l[mi], b[nj][0], b[nj][2]);
                    mma16816(acc[mi][nj*2+1], a_l[mi], b[nj][1], b[nj][3]);
                }
            #pragma unroll
            for (int nj = 0; nj < 4; nj++) {
                int row = wn*64 + nj*16 + (lane & 7) + ((lane >> 3) & 1)*8;
                uint32_t off = OFF_NT(row, c);
                ldsm_x4(b[nj][0], b[nj][1], b[nj][2], b[nj][3], sBlo + off);
            }
            #pragma unroll
            for (int mi = 0; mi < 2; mi++)
                #pragma unroll
                for (int nj = 0; nj < 4; nj++) {
                    mma16816(acc[mi][nj*2],   a_h[mi], b[nj][0], b[nj][2]);
                    mma16816(acc[mi][nj*2+1], a_h[mi], b[nj][1], b[nj][3]);
                }
        }
        __syncthreads();
        if (kc + 3 < 8) load_chunk(kc + 3);
    }

    int g = lane >> 2, tg = lane & 3;
    #pragma unroll
    for (int mi = 0; mi < 2; mi++) {
        int r0 = wm*32 + mi*16 + g;
        float bv0 = bias ? bias[r0]   : 0.f;
        float bv1 = bias ? bias[r0+8] : 0.f;
        #pragma unroll
        for (int nt = 0; nt < 8; nt++) {
            int col = wn*64 + nt*8 + tg*2;
            float2 v0 = make_float2(acc[mi][nt][0] + bv0, acc[mi][nt][1] + bv0);
            float2 v1 = make_float2(acc[mi][nt][2] + bv1, acc[mi][nt][3] + bv1);
            *(float2*)&D[(size_t)r0*ldD + col]     = v0;
            *(float2*)&D[(size_t)(r0+8)*ldD + col] = v1;
        }
    }
}

// ============================================================
// GEMM core, A k-major [128 m][256 k], B row-major [256 k][N] (ldB stride).
// ============================================================
__device__ __forceinline__ void gemm_kn(
    const __nv_bfloat16* __restrict__ Ahi, const __nv_bfloat16* __restrict__ Alo,
    const __nv_bfloat16* __restrict__ Bhi, const __nv_bfloat16* __restrict__ Blo,
    size_t ldB,
    float* __restrict__ D, int ldD, const float* __restrict__ bias, uint32_t sm)
{
    int tid = threadIdx.x;
    int wid = tid >> 5, lane = tid & 31;
    int wm = wid >> 1, wn = wid & 1;

    float acc[2][8][4];
    #pragma unroll
    for (int i=0;i<2;i++) for (int j=0;j<8;j++) for (int q=0;q<4;q++) acc[i][j][q] = 0.f;

    auto load_chunk = [&](int kc) {
        uint32_t base = sm + (kc % 3)*STG;
        #pragma unroll
        for (int e = tid; e < 512; e += 256) {
            int row = e >> 2, c = e & 3;
            uint32_t off = OFF_NT(row, c);
            size_t gA = (size_t)row*256 + kc*32 + c*8;
            cp16(base         + off, Ahi + gA);
            cp16(base +  8192 + off, Alo + gA);
            int kr = e >> 4, c16 = e & 15;
            uint32_t offb = OFF_T(kr, c16);
            size_t gB = (size_t)(kc*32 + kr)*ldB + c16*8;
            cp16(base + 16384 + offb, Bhi + gB);
            cp16(base + 24576 + offb, Blo + gB);
        }
        CP_COMMIT();
    };

    load_chunk(0); load_chunk(1); load_chunk(2);

    #pragma unroll 1
    for (int kc = 0; kc < 8; kc++) {
        if (kc < 6)      asm volatile("cp.async.wait_group 2;" ::: "memory");
        else if (kc == 6) asm volatile("cp.async.wait_group 1;" ::: "memory");
        else             asm volatile("cp.async.wait_group 0;" ::: "memory");
        __syncthreads();

        uint32_t base = sm + (kc % 3)*STG;
        uint32_t sAhi = base, sAlo = base + 8192, sBhi = base + 16384, sBlo = base + 24576;

        #pragma unroll
        for (int ks = 0; ks < 2; ks++) {
            int c = ks*2 + (lane >> 4);
            uint32_t a_h[2][4], a_l[2][4];
            #pragma unroll
            for (int mi = 0; mi < 2; mi++) {
                int row = wm*32 + mi*16 + (lane & 15);
                uint32_t off = OFF_NT(row, c);
                ldsm_x4(a_h[mi][0], a_h[mi][1], a_h[mi][2], a_h[mi][3], sAhi + off);
                ldsm_x4(a_l[mi][0], a_l[mi][1], a_l[mi][2], a_l[mi][3], sAlo + off);
            }
            int kr = ks*16 + (lane & 7) + ((lane >> 3) & 1)*8;
            uint32_t b[4][4];
            #pragma unroll
            for (int nj = 0; nj < 4; nj++) {
                int n = wn*64 + nj*16 + ((lane >> 4) & 1)*8;
                uint32_t off = OFF_T(kr, (n >> 3));
                ldsm_x4_t(b[nj][0], b[nj][1], b[nj][2], b[nj][3], sBhi + off);
            }
            #pragma unroll
            for (int mi = 0; mi < 2; mi++)
                #pragma unroll
                for (int nj = 0; nj < 4; nj++) {
                    mma16816(acc[mi][nj*2],   a_h[mi], b[nj][0], b[nj][1]);
                    mma16816(acc[mi][nj*2+1], a_h[mi], b[nj][2], b[nj][3]);
                }
            #pragma unroll
            for (int mi = 0; mi < 2; mi++)
                #pragma unroll
                for (int nj = 0; nj < 4; nj++) {
                    mma16816(acc[mi][nj*2],   a_l[mi], b[nj][0], b[nj][1]);
                    mma16816(acc[mi][nj*2+1], a_l[mi], b[nj][2], b[nj][3]);
                }
            #pragma unroll
            for (int nj = 0; nj < 4; nj++) {
                int n = wn*64 + nj*16 + ((lane >> 4) & 1)*8;
                uint32_t off = OFF_T(kr, (n >> 3));
                ldsm_x4_t(b[nj][0], b[nj][1], b[nj][2], b[nj][3], sBlo + off);
            }
            #pragma unroll
            for (int mi = 0; mi < 2; mi++)
                #pragma unroll
                for (int nj = 0; nj < 4; nj++) {
                    mma16816(acc[mi][nj*2],   a_h[mi], b[nj][0], b[nj][1]);
                    mma16816(acc[mi][nj*2+1], a_h[mi], b[nj][2], b[nj][3]);
                }
        }
        __syncthreads();
        if (kc + 3 < 8) load_chunk(kc + 3);
    }

    int g = lane >> 2, tg = lane & 3;
    #pragma unroll
    for (int mi = 0; mi < 2; mi++) {
        int r0 = wm*32 + mi*16 + g;
        float bv0 = bias ? bias[r0]   : 0.f;
        float bv1 = bias ? bias[r0+8] : 0.f;
        #pragma unroll
        for (int nt = 0; nt < 8; nt++) {
            int col = wn*64 + nt*8 + tg*2;
            float2 v0 = make_float2(acc[mi][nt][0] + bv0, acc[mi][nt][1] + bv0);
            float2 v1 = make_float2(acc[mi][nt][2] + bv1, acc[mi][nt][3] + bv1);
            *(float2*)&D[(size_t)r0*ldD + col]     = v0;
            *(float2*)&D[(size_t)(r0+8)*ldD + col] = v1;
        }
    }
}

// ============================================================
// Stage 1: rfft(512) per row via packed radix-4 256-pt FFT.
// 512 threads, 16 rows/block. Output bf16 hi/lo, [m][row].
// ============================================================
__global__ void __launch_bounds__(512) k_fft_fwd(const float* __restrict__ x) {
    __shared__ float sre[16*288];
    __shared__ float sim[16*288];
    __shared__ float2 tw[256];          // e^{-2pi i t/256}
    __shared__ float uer[129], uei[129];
    int tid = threadIdx.x;
    if (tid < 256) { float s,c; sincosf(6.283185307179586f*(float)tid/256.0f,&s,&c); tw[tid]=make_float2(c,-s); }
    if (tid < 129) { float s,c; sincosf(-6.283185307179586f*(float)tid/512.0f,&s,&c); uer[tid]=c; uei[tid]=s; }
    __syncthreads();
    int w = tid >> 5, lane = tid & 31;
    float* re = sre + w*288;
    float* im = sim + w*288;
    int row = blockIdx.x*16 + w;
    const float4* xr4 = (const float4*)(x + (size_t)row*512);
    #pragma unroll
    for (int j = 0; j < 4; j++) {
        float4 v = xr4[lane + 32*j];
        int f  = lane + 32*j;
        int r0 = __brev(2*f)   >> 24;
        int r1 = __brev(2*f+1) >> 24;
        re[SWF(r0)]=v.x; im[SWF(r0)]=v.y;
        re[SWF(r1)]=v.z; im[SWF(r1)]=v.w;
    }
    __syncwarp();
    // round Q=1 (no twiddle), float4 vectorized
    #pragma unroll
    for (int h = 0; h < 2; h++) {
        int p = 4*(lane + 32*h);
        int a = SWF(p);
        float4 vr = *(float4*)&re[a];
        float4 vi = *(float4*)&im[a];
        float t0r=vr.x,t0i=vi.x, t1r=vr.z,t1i=vi.z, t2r=vr.y,t2i=vi.y, t3r=vr.w,t3i=vi.w;
        float s0r=t0r+t2r, s0i=t0i+t2i, d0r=t0r-t2r, d0i=t0i-t2i;
        float s1r=t1r+t3r, s1i=t1i+t3i, d1r=t1r-t3r, d1i=t1i-t3i;
        float4 yr, yi;
        yr.x = s0r+s1r; yi.x = s0i+s1i;        // y0
        yr.y = d0r+d1i; yi.y = d0i-d1r;        // y1 = d0 - i*d1
        yr.z = s0r-s1r; yi.z = s0i-s1i;        // y2
        yr.w = d0r-d1i; yi.w = d0i+d1r;        // y3 = d0 + i*d1
        *(float4*)&re[a] = yr; *(float4*)&im[a] = yi;
    }
    __syncwarp();
    // rounds Q=4,16,64
    #pragma unroll
    for (int rq = 0; rq < 3; rq++) {
        int Q = 4 << (2*rq);
        int step = 16 >> (2*rq);
        #pragma unroll
        for (int h = 0; h < 2; h++) {
            int b = lane + 32*h;
            int j = b & (Q-1);
            int p = ((b & ~(Q-1)) << 2) + j;
            float2 w1 = tw[(j*step) & 255];
            float2 w2 = tw[(2*j*step) & 255];
            float2 w3 = tw[(3*j*step) & 255];
            int a0 = SWF(p), a1 = SWF(p+2*Q), a2 = SWF(p+Q), a3 = SWF(p+3*Q);
            float x0r=re[a0], x0i=im[a0];
            float x1r=re[a1], x1i=im[a1];
            float x2r=re[a2], x2i=im[a2];
            float x3r=re[a3], x3i=im[a3];
            float t1r = x1r*w1.x - x1i*w1.y, t1i = x1r*w1.y + x1i*w1.x;
            float t2r = x2r*w2.x - x2i*w2.y, t2i = x2r*w2.y + x2i*w2.x;
            float t3r = x3r*w3.x - x3i*w3.y, t3i = x3r*w3.y + x3i*w3.x;
            float s0r=x0r+t2r, s0i=x0i+t2i, d0r=x0r-t2r, d0i=x0i-t2i;
            float s1r=t1r+t3r, s1i=t1i+t3i, d1r=t1r-t3r, d1i=t1i-t3i;
            re[a0]=s0r+s1r; im[a0]=s0i+s1i;    // y0 -> p
            re[a2]=d0r+d1i; im[a2]=d0i-d1r;    // y1 -> p+Q
            re[a1]=s0r-s1r; im[a1]=s0i-s1i;    // y2 -> p+2Q
            re[a3]=d0r-d1i; im[a3]=d0i+d1r;    // y3 -> p+3Q
        }
        __syncwarp();
    }
    const float SC = 0.012271846303085129f;  // 2*pi/512
    float ro[5], io[5];
    #pragma unroll
    for (int j = 0; j < 5; j++) {
        int k = lane + 32*j;
        if (k <= 128) {
            int km = (256-k) & 255;
            float zr=re[SWF(k)],  zi= im[SWF(k)];
            float mr=re[SWF(km)], mi=-im[SWF(km)];
            float er=0.5f*(zr+mr), ei=0.5f*(zi+mi);
            float dr=0.5f*(zr-mr), di=0.5f*(zi-mi);
            float pr=di, pi=-dr;
            float wr=uer[k], wi=uei[k];
            float qr=pr*wr-pi*wi, qi=pr*wi+pi*wr;
            ro[j] = (er+qr)*SC;
            io[j] = (ei+qi)*SC;
        }
    }
    __syncthreads();
    float* ore = sre;   // reuse: [129][16]
    float* oim = sim;
    #pragma unroll
    for (int j = 0; j < 5; j++) {
        int k = lane + 32*j;
        if (k <= 128) { ore[k*16+w] = ro[j]; oim[k*16+w] = io[j]; }
    }
    __syncthreads();
    int base = blockIdx.x*16;
    for (int idx = tid; idx < 129*16; idx += 512) {
        int m = idx >> 4, r = idx & 15;
        size_t o = (size_t)m*ROWS1 + base + r;
        __nv_bfloat16 h, l;
        split2(ore[idx], h, l); d_Xr_hi[o]=h; d_Xr_lo[o]=l;
        split2(oim[idx], h, l); d_Xi_hi[o]=h; d_Xi_lo[o]=l;
    }
}

// ============================================================
// Stage 2: At[m][klo][kh] = sum_l wmat[m][l][kh]*pct[m][l][klo], bf16 hi/lo.
// ============================================================
__global__ void k_buildA(const float* __restrict__ wmat, const float* __restrict__ pct) {
    int m    = blockIdx.z;
    int kh0  = blockIdx.x * 64;
    int klo0 = blockIdx.y * 64;
    __shared__ float sW[16][65];
    __shared__ float sP[16][64];
    int tid = threadIdx.x;
    int tx = tid & 15, ty = tid >> 4;
    float acc[4][4] = {};
    const float* wbase = wmat + m*LMAX*HHI;
    const float* pbase = pct  + m*LMAX*HLO;
    for (int l0 = 0; l0 < 128; l0 += 16) {
        #pragma unroll
        for (int q = 0; q < 4; q++) {
            int e = tid + q*256;
            int li = e >> 6, ki = e & 63;
            sW[li][ki] = wbase[(l0+li)*HHI + kh0  + ki];
            sP[li][ki] = pbase[(l0+li)*HLO + klo0 + ki];
        }
        __syncthreads();
        #pragma unroll
        for (int l = 0; l < 16; l++) {
            float a[4], b[4];
            #pragma unroll
            for (int i=0;i<4;i++) a[i]=sW[l][ty*4+i];
            #pragma unroll
            for (int j=0;j<4;j++) b[j]=sP[l][tx*4+j];
            #pragma unroll
            for (int i=0;i<4;i++)
                #pragma unroll
                for (int j=0;j<4;j++) acc[i][j] += a[i]*b[j];
        }
        __syncthreads();
    }
    size_t Abase = (size_t)m*(HLO*HHI);
    #pragma unroll
    for (int j=0;j<4;j++) {
        int klo = klo0 + tx*4 + j;
        __nv_bfloat162 ph0, ph1, pl0, pl1;
        __nv_bfloat16 h, l;
        split2(acc[0][j], h, l); ph0.x=h; pl0.x=l;
        split2(acc[1][j], h, l); ph0.y=h; pl0.y=l;
        split2(acc[2][j], h, l); ph1.x=h; pl1.x=l;
        split2(acc[3][j], h, l); ph1.y=h; pl1.y=l;
        size_t o = Abase + (size_t)klo*HHI + kh0 + ty*4;
        *(__nv_bfloat162*)&d_At_hi[o]   = ph0;
        *(__nv_bfloat162*)&d_At_hi[o+2] = ph1;
        *(__nv_bfloat162*)&d_At_lo[o]   = pl0;
        *(__nv_bfloat162*)&d_At_lo[o+2] = pl1;
    }
}

// ============================================================
// Stage 2b: split conv weights to bf16 hi/lo
// ============================================================
__global__ void k_wsplit(const float* __restrict__ w) {
    int i = blockIdx.x*256 + threadIdx.x;   // 65536 total
    __nv_bfloat16 h, l;
    split2(w[i], h, l);
    d_Whi[i] = h; d_Wlo[i] = l;
}

// ============================================================
// Stage 3: Legendre per-m GEMM.
// ============================================================
__global__ void __launch_bounds__(256) k_legendre_mma() {
    extern __shared__ __align__(128) char dsm[];
    int m = blockIdx.y;
    int bx = blockIdx.x;
    int half = bx >> 2;
    int bc0  = (bx & 3) * 128;
    size_t xo = (size_t)m*ROWS1 + (size_t)bc0*HHI;
    const __nv_bfloat16 *Ah, *Al;
    float* D;
    if (half) { Ah = d_Xi_hi + xo; Al = d_Xi_lo + xo; D = d_Gi; }
    else      { Ah = d_Xr_hi + xo; Al = d_Xr_lo + xo; D = d_Gr; }
    D += (size_t)m*ROWS2 + (size_t)bc0*HLO;
    const __nv_bfloat16* Bh = d_At_hi + (size_t)m*(HLO*HHI);
    const __nv_bfloat16* Bl = d_At_lo + (size_t)m*(HLO*HHI);
    gemm_nn(Ah, Al, Bh, Bl, D, HLO, nullptr, smem_u32(dsm));
}

// ============================================================
// Stage 4: irfft(n=256)*256 per row via packed radix-4 128-pt inverse FFT.
// ============================================================
__global__ void k_ifft() {
    __shared__ float gre[129*8], gim[129*8];
    __shared__ float sre[8*144], sim[8*144];
    __shared__ float2 tw2[128];          // e^{+2pi i t/128}
    __shared__ float wqr[128], wqi[128]; // e^{+2pi i k/256}
    int tid = threadIdx.x;
    if (tid < 128){ float s,c; sincosf(6.283185307179586f*(float)tid/128.f,&s,&c); tw2[tid]=make_float2(c,s); }
    if (tid < 128){ float s,c; sincosf(6.283185307179586f*(float)tid/256.f,&s,&c); wqr[tid]=c; wqi[tid]=s; }
    int base = blockIdx.x*8;
    for (int idx = tid; idx < 129*8; idx += 256) {
        int m = idx >> 3, r = idx & 7;
        gre[idx] = d_Gr[m*ROWS2 + base + r];
        gim[idx] = d_Gi[m*ROWS2 + base + r];
    }
    __syncthreads();
    int w = tid >> 5, lane = tid & 31;
    float* re = sre + w*144;
    float* im = sim + w*144;
    #pragma unroll 4
    for (int k = lane; k < 128; k += 32) {
        float ar = gre[k*8+w],        ai =  gim[k*8+w];
        float br = gre[(128-k)*8+w],  bi = -gim[(128-k)*8+w];
        float wr = wqr[k], wi = wqi[k];
        float c1r = 1.f - wi, c1i =  wr;
        float c2r = 1.f + wi, c2i = -wr;
        float Zr = ar*c1r - ai*c1i + br*c2r - bi*c2i;
        float Zi = ar*c1i + ai*c1r + br*c2i + bi*c2r;
        int rv = __brev(k) >> 25;
        re[SWF(rv)] = Zr; im[SWF(rv)] = Zi;
    }
    __syncwarp();
    // round Q=1 (no twiddle), inverse signs, float4
    {
        int p = 4*lane;
        int a = SWF(p);
        float4 vr = *(float4*)&re[a];
        float4 vi = *(float4*)&im[a];
        float t0r=vr.x,t0i=vi.x, t1r=vr.z,t1i=vi.z, t2r=vr.y,t2i=vi.y, t3r=vr.w,t3i=vi.w;
        float s0r=t0r+t2r, s0i=t0i+t2i, d0r=t0r-t2r, d0i=t0i-t2i;
        float s1r=t1r+t3r, s1i=t1i+t3i, d1r=t1r-t3r, d1i=t1i-t3i;
        float4 yr, yi;
        yr.x = s0r+s1r; yi.x = s0i+s1i;        // y0
        yr.y = d0r-d1i; yi.y = d0i+d1r;        // y1 = d0 + i*d1
        yr.z = s0r-s1r; yi.z = s0i-s1i;        // y2
        yr.w = d0r+d1i; yi.w = d0i-d1r;        // y3 = d0 - i*d1
        *(float4*)&re[a] = yr; *(float4*)&im[a] = yi;
    }
    __syncwarp();
    // rounds Q=4 (step=8), Q=16 (step=2)
    #pragma unroll
    for (int rq = 0; rq < 2; rq++) {
        int Q = 4 << (2*rq);
        int step = 8 >> (2*rq);
        int b = lane;
        int j = b & (Q-1);
        int p = ((b & ~(Q-1)) << 2) + j;
        float2 w1 = tw2[(j*step) & 127];
        float2 w2 = tw2[(2*j*step) & 127];
        float2 w3 = tw2[(3*j*step) & 127];
        int a0 = SWF(p), a1 = SWF(p+2*Q), a2 = SWF(p+Q), a3 = SWF(p+3*Q);
        float x0r=re[a0], x0i=im[a0];
        float x1r=re[a1], x1i=im[a1];
        float x2r=re[a2], x2i=im[a2];
        float x3r=re[a3], x3i=im[a3];
        float t1r = x1r*w1.x - x1i*w1.y, t1i = x1r*w1.y + x1i*w1.x;
        float t2r = x2r*w2.x - x2i*w2.y, t2i = x2r*w2.y + x2i*w2.x;
        float t3r = x3r*w3.x - x3i*w3.y, t3i = x3r*w3.y + x3i*w3.x;
        float s0r=x0r+t2r, s0i=x0i+t2i, d0r=x0r-t2r, d0i=x0i-t2i;
        float s1r=t1r+t3r, s1i=t1i+t3i, d1r=t1r-t3r, d1i=t1i-t3i;
        re[a0]=s0r+s1r; im[a0]=s0i+s1i;    // y0
        re[a2]=d0r-d1i; im[a2]=d0i+d1r;    // y1 = d0 + i*d1
        re[a1]=s0r-s1r; im[a1]=s0i-s1i;    // y2
        re[a3]=d0r+d1i; im[a3]=d0i-d1r;    // y3 = d0 - i*d1
        __syncwarp();
    }
    // final radix-2 stage, half=64
    #pragma unroll
    for (int h = 0; h < 2; h++) {
        int p = lane + 32*h;
        float2 wv = tw2[p];
        int a0 = SWF(p), a1 = SWF(p+64);
        float x0r=re[a0], x0i=im[a0];
        float x1r=re[a1], x1i=im[a1];
        float tr = x1r*wv.x - x1i*wv.y, ti = x1r*wv.y + x1i*wv.x;
        re[a0]=x0r+tr; im[a0]=x0i+ti;
        re[a1]=x0r-tr; im[a1]=x0i-ti;
    }
    __syncwarp();
    // y[2n] = Re z[n], y[2n+1] = Im z[n]; store bf16 hi/lo pairs
    __nv_bfloat162* yh = (__nv_bfloat162*)d_Yc_hi + (size_t)(base + w)*128;
    __nv_bfloat162* yl = (__nv_bfloat162*)d_Yc_lo + (size_t)(base + w)*128;
    #pragma unroll 4
    for (int n = lane; n < 128; n += 32) {
        __nv_bfloat16 h0,l0,h1,l1;
        split2(re[SWF(n)], h0, l0);
        split2(im[SWF(n)], h1, l1);
        __nv_bfloat162 vh; vh.x=h0; vh.y=h1;
        __nv_bfloat162 vl; vl.x=l0; vl.y=l1;
        yh[n] = vh; yl[n] = vl;
    }
}

// ============================================================
// Stage 5: 1x1 conv. D[o][hw] = W[o][c] * Y[c][hw]
// ============================================================
__global__ void __launch_bounds__(256) k_conv_mma(const float* __restrict__ bias) {
    extern __shared__ __align__(128) char dsm[];
    int b = blockIdx.z, o0 = blockIdx.y*128, hw0 = blockIdx.x*128;
    const __nv_bfloat16* Ah = d_Whi + (size_t)o0*CIN;
    const __nv_bfloat16* Al = d_Wlo + (size_t)o0*CIN;
    const __nv_bfloat16* Bh = d_Yc_hi + (size_t)b*CIN*HWLO + hw0;
    const __nv_bfloat16* Bl = d_Yc_lo + (size_t)b*CIN*HWLO + hw0;
    float* D = d_H + ((size_t)b*COUT + o0)*HWLO + hw0;
    gemm_kn(Ah, Al, Bh, Bl, (size_t)HWLO, D, HWLO, bias + o0, smem_u32(dsm));
}

// ============================================================
// Stage 6: GroupNorm stats — two-phase deterministic reduction.
// ============================================================
__global__ void k_gnstat1() {
    int blk = blockIdx.x;             // 512 = 64 groups * 8 parts
    int bg = blk >> 3, part = blk & 7;
    const float* hb = d_H + (size_t)bg*(CPG*HWLO) + part*32768;
    double s = 0.0, s2 = 0.0;
    for (int i = threadIdx.x; i < 32768; i += 256) {
        float v = hb[i];
        s += (double)v; s2 += (double)v*(double)v;
    }
    __shared__ double sh[256], sh2[256];
    sh[threadIdx.x] = s; sh2[threadIdx.x] = s2;
    __syncthreads();
    for (int st = 128; st > 0; st >>= 1) {
        if (threadIdx.x < st) { sh[threadIdx.x] += sh[threadIdx.x+st]; sh2[threadIdx.x] += sh2[threadIdx.x+st]; }
        __syncthreads();
    }
    if (threadIdx.x == 0) { d_ps[blk] = sh[0]; d_ps2[blk] = sh2[0]; }
}
__global__ void k_gnstat2() {
    int bg = threadIdx.x;             // 64 threads
    double s = 0.0, s2 = 0.0;
    #pragma unroll
    for (int p = 0; p < 8; p++) { s += d_ps[bg*8+p]; s2 += d_ps2[bg*8+p]; }
    const double N = (double)(CPG*HWLO);
    double mean = s / N;
    double var  = s2 / N - mean*mean;
    d_mean[bg] = (float)mean;
    d_rstd[bg] = rsqrtf((float)var + 1e-5f);
}

// ============================================================
// Stage 7: normalize + affine + exact GELU
// ============================================================
__global__ void k_gnapply(const float* __restrict__ gamma, const float* __restrict__ beta,
                          float* __restrict__ out) {
    int idx = blockIdx.x*256 + threadIdx.x;
    int fidx = idx * 4;
    int o  = (fidx >> 15) & 255;
    int bg = fidx >> 18;
    float a  = gamma[o] * d_rstd[bg];
    float b2 = beta[o] - d_mean[bg] * a;
    float4 h = ((const float4*)d_H)[idx];
    float v0 = h.x*a + b2, v1 = h.y*a + b2, v2 = h.z*a + b2, v3 = h.w*a + b2;
    float4 r;
    r.x = v0 * normcdff(v0);
    r.y = v1 * normcdff(v1);
    r.z = v2 * normcdff(v2);
    r.w = v3 * normcdff(v3);
    ((float4*)out)[idx] = r;
}

// ============================================================
extern "C" void kernel_launch(void* const* d_in, const int* in_sizes, int n_in,
                              void* d_out, int out_size) {
    const float* x      = (const float*)d_in[0];
    const float* conv_w = (const float*)d_in[1];
    const float* conv_b = (const float*)d_in[2];
    const float* gamma  = (const float*)d_in[3];
    const float* beta   = (const float*)d_in[4];
    const float* wmat   = (const float*)d_in[5];
    const float* pct    = (const float*)d_in[6];
    float* out = (float*)d_out;

    cudaFuncSetAttribute(k_legendre_mma, cudaFuncAttributeMaxDynamicSharedMemorySize, GEMM_SMEM);
    cudaFuncSetAttribute(k_conv_mma,     cudaFuncAttributeMaxDynamicSharedMemorySize, GEMM_SMEM);

    k_fft_fwd     <<<ROWS1/16, 512>>>(x);
    k_buildA      <<<dim3(4,2,MMAX), 256>>>(wmat, pct);
    k_wsplit      <<<256, 256>>>(conv_w);
    k_legendre_mma<<<dim3(8, MMAX), 256, GEMM_SMEM>>>();
    k_ifft        <<<ROWS2/8, 256>>>();
    k_conv_mma    <<<dim3(HWLO/128, COUT/128, BATCH), 256, GEMM_SMEM>>>(conv_b);
    k_gnstat1     <<<512, 256>>>();
    k_gnstat2     <<<1, 64>>>();
    k_gnapply     <<<(BC*HWLO)/4/256, 256>>>(gamma, beta, out);
}

// round 8
// speedup vs baseline: 1.5491x; 1.1444x over previous
#include <cuda_runtime.h>
#include <cuda_bf16.h>
#include <math.h>
#include <stdint.h>

#define BATCH 2
#define CIN 256
#define COUT 256
#define HHI 256
#define WHI 512
#define HLO 128
#define WLO 256
#define MMAX 129
#define LMAX 128
#define CPG 8
#define BC (BATCH*CIN)          /* 512    */
#define ROWS1 (BC*HHI)          /* 131072 */
#define ROWS2 (BC*HLO)          /* 65536  */
#define HWLO (HLO*WLO)          /* 32768  */

// -------- scratch (static device globals; no allocation allowed) --------
__device__ __align__(16) __nv_bfloat16 d_Xr_hi[MMAX*ROWS1];
__device__ __align__(16) __nv_bfloat16 d_Xr_lo[MMAX*ROWS1];
__device__ __align__(16) __nv_bfloat16 d_Xi_hi[MMAX*ROWS1];
__device__ __align__(16) __nv_bfloat16 d_Xi_lo[MMAX*ROWS1];
__device__ __align__(16) __nv_bfloat16 d_At_hi[MMAX*HLO*HHI];   // [m][klo][kh]
__device__ __align__(16) __nv_bfloat16 d_At_lo[MMAX*HLO*HHI];
__device__ __align__(16) __nv_bfloat16 d_Wm_hi[MMAX*LMAX*HHI];  // wmat split [m][l][kh]
__device__ __align__(16) __nv_bfloat16 d_Wm_lo[MMAX*LMAX*HHI];
__device__ __align__(16) __nv_bfloat16 d_P_hi [MMAX*LMAX*HLO];  // pct split [m][l][klo]
__device__ __align__(16) __nv_bfloat16 d_P_lo [MMAX*LMAX*HLO];
__device__ __align__(16) __nv_bfloat16 d_Whi[COUT*CIN];
__device__ __align__(16) __nv_bfloat16 d_Wlo[COUT*CIN];
__device__ float d_Gr[MMAX*ROWS2];        // [m][bc*128+klo]
__device__ float d_Gi[MMAX*ROWS2];
__device__ __align__(16) __nv_bfloat16 d_Yc_hi[BC*HWLO];  // [b][c][hw]
__device__ __align__(16) __nv_bfloat16 d_Yc_lo[BC*HWLO];
__device__ float d_H [BC*HWLO];           // [b][o][hw]
__device__ float d_cps[1024*16], d_cps2[1024*16];
__device__ float d_mean[BATCH*32];
__device__ float d_rstd[BATCH*32];

// ======================= helpers =======================
__device__ __forceinline__ uint32_t smem_u32(const void* p) {
    uint32_t a;
    asm("{ .reg .u64 t; cvta.to.shared.u64 t, %1; cvt.u32.u64 %0, t; }" : "=r"(a) : "l"(p));
    return a;
}
__device__ __forceinline__ void ldsm_x4(uint32_t& r0, uint32_t& r1, uint32_t& r2, uint32_t& r3, uint32_t addr) {
    asm volatile("ldmatrix.sync.aligned.m8n8.x4.shared.b16 {%0,%1,%2,%3}, [%4];"
        : "=r"(r0), "=r"(r1), "=r"(r2), "=r"(r3) : "r"(addr));
}
__device__ __forceinline__ void ldsm_x4_t(uint32_t& r0, uint32_t& r1, uint32_t& r2, uint32_t& r3, uint32_t addr) {
    asm volatile("ldmatrix.sync.aligned.m8n8.x4.trans.shared.b16 {%0,%1,%2,%3}, [%4];"
        : "=r"(r0), "=r"(r1), "=r"(r2), "=r"(r3) : "r"(addr));
}
__device__ __forceinline__ void mma16816(float* d, const uint32_t* a, uint32_t b0, uint32_t b1) {
    asm volatile("mma.sync.aligned.m16n8k16.row.col.f32.bf16.bf16.f32 "
        "{%0,%1,%2,%3}, {%4,%5,%6,%7}, {%8,%9}, {%0,%1,%2,%3};"
        : "+f"(d[0]), "+f"(d[1]), "+f"(d[2]), "+f"(d[3])
        : "r"(a[0]), "r"(a[1]), "r"(a[2]), "r"(a[3]), "r"(b0), "r"(b1));
}
__device__ __forceinline__ void cp16(uint32_t dst, const void* src) {
    asm volatile("cp.async.cg.shared.global [%0], [%1], 16;" :: "r"(dst), "l"(src));
}
#define CP_COMMIT() asm volatile("cp.async.commit_group;" ::: "memory")
__device__ __forceinline__ void split2(float v, __nv_bfloat16& h, __nv_bfloat16& l) {
    h = __float2bfloat16(v);
    l = __float2bfloat16(v - __bfloat162float(h));
}

// stage layout: 4 tiles x 8KB = 32KB; 3 stages = 96KB
#define STG (32768)
#define GEMM_SMEM (3*STG)

// non-trans tile [128 rows][32 k], 64B rows, swizzle c^((row>>1)&3)
#define OFF_NT(row, c) ((uint32_t)((row)<<6) + (uint32_t)(((c) ^ (((row)>>1)&3)) << 4))
// trans tile [32 k][128 n], 256B rows, swizzle c^(k&7)
#define OFF_T(k, c16)  ((uint32_t)((k)<<8) + (uint32_t)(((c16) ^ ((k)&7)) << 4))

// smem FFT pad
#define SWF(i) ((i) + ((((i)>>5))<<2))

// ============================================================
// GEMM core, both operands k-major: D[128m][128n] = A[128][256] B[128][256]^T
// ============================================================
__device__ __forceinline__ void gemm_nn(
    const __nv_bfloat16* __restrict__ Ahi, const __nv_bfloat16* __restrict__ Alo,
    const __nv_bfloat16* __restrict__ Bhi, const __nv_bfloat16* __restrict__ Blo,
    float* __restrict__ D, int ldD, uint32_t sm)
{
    int tid = threadIdx.x;
    int wid = tid >> 5, lane = tid & 31;
    int wm = wid >> 1, wn = wid & 1;

    float acc[2][8][4];
    #pragma unroll
    for (int i=0;i<2;i++) for (int j=0;j<8;j++) for (int q=0;q<4;q++) acc[i][j][q] = 0.f;

    auto load_chunk = [&](int kc) {
        uint32_t base = sm + (kc % 3)*STG;
        #pragma unroll
        for (int e = tid; e < 512; e += 256) {
            int row = e >> 2, c = e & 3;
            uint32_t off = OFF_NT(row, c);
            size_t g = (size_t)row*256 + kc*32 + c*8;
            cp16(base          + off, Ahi + g);
            cp16(base +  8192  + off, Alo + g);
            cp16(base + 16384  + off, Bhi + g);
            cp16(base + 24576  + off, Blo + g);
        }
        CP_COMMIT();
    };

    load_chunk(0); load_chunk(1); load_chunk(2);

    #pragma unroll 1
    for (int kc = 0; kc < 8; kc++) {
        if (kc < 6)      asm volatile("cp.async.wait_group 2;" ::: "memory");
        else if (kc == 6) asm volatile("cp.async.wait_group 1;" ::: "memory");
        else             asm volatile("cp.async.wait_group 0;" ::: "memory");
        __syncthreads();

        uint32_t base = sm + (kc % 3)*STG;
        uint32_t sAhi = base, sAlo = base + 8192, sBhi = base + 16384, sBlo = base + 24576;

        #pragma unroll
        for (int ks = 0; ks < 2; ks++) {
            int c = ks*2 + (lane >> 4);
            uint32_t a_h[2][4], a_l[2][4];
            #pragma unroll
            for (int mi = 0; mi < 2; mi++) {
                int row = wm*32 + mi*16 + (lane & 15);
                uint32_t off = OFF_NT(row, c);
                ldsm_x4(a_h[mi][0], a_h[mi][1], a_h[mi][2], a_h[mi][3], sAhi + off);
                ldsm_x4(a_l[mi][0], a_l[mi][1], a_l[mi][2], a_l[mi][3], sAlo + off);
            }
            uint32_t b[4][4];
            #pragma unroll
            for (int nj = 0; nj < 4; nj++) {
                int row = wn*64 + nj*16 + (lane & 7) + ((lane >> 3) & 1)*8;
                uint32_t off = OFF_NT(row, c);
                ldsm_x4(b[nj][0], b[nj][1], b[nj][2], b[nj][3], sBhi + off);
            }
            #pragma unroll
            for (int mi = 0; mi < 2; mi++)
                #pragma unroll
                for (int nj = 0; nj < 4; nj++) {
                    mma16816(acc[mi][nj*2],   a_h[mi], b[nj][0], b[nj][2]);
                    mma16816(acc[mi][nj*2+1], a_h[mi], b[nj][1], b[nj][3]);
                }
            #pragma unroll
            for (int mi = 0; mi < 2; mi++)
                #pragma unroll
                for (int nj = 0; nj < 4; nj++) {
                    mma16816(acc[mi][nj*2],   a_l[mi], b[nj][0], b[nj][2]);
                    mma16816(acc[mi][nj*2+1], a_l[mi], b[nj][1], b[nj][3]);
                }
            #pragma unroll
            for (int nj = 0; nj < 4; nj++) {
                int row = wn*64 + nj*16 + (lane & 7) + ((lane >> 3) & 1)*8;
                uint32_t off = OFF_NT(row, c);
                ldsm_x4(b[nj][0], b[nj][1], b[nj][2], b[nj][3], sBlo + off);
            }
            #pragma unroll
            for (int mi = 0; mi < 2; mi++)
                #pragma unroll
                for (int nj = 0; nj < 4; nj++) {
                    mma16816(acc[mi][nj*2],   a_h[mi], b[nj][0], b[nj][2]);
                    mma16816(acc[mi][nj*2+1], a_h[mi], b[nj][1], b[nj][3]);
                }
        }
        __syncthreads();
        if (kc + 3 < 8) load_chunk(kc + 3);
    }

    int g = lane >> 2, tg = lane & 3;
    #pragma unroll
    for (int mi = 0; mi < 2; mi++) {
        int r0 = wm*32 + mi*16 + g;
        #pragma unroll
        for (int nt = 0; nt < 8; nt++) {
            int col = wn*64 + nt*8 + tg*2;
            *(float2*)&D[(size_t)r0*ldD + col]     = make_float2(acc[mi][nt][0], acc[mi][nt][1]);
            *(float2*)&D[(size_t)(r0+8)*ldD + col] = make_float2(acc[mi][nt][2], acc[mi][nt][3]);
        }
    }
}

// ============================================================
// GEMM core, A k-major [128 m][256 k], B row-major [256 k][N] (ldB stride).
// Optional fused GroupNorm partial stats (cps != nullptr).
// ============================================================
__device__ __forceinline__ void gemm_kn(
    const __nv_bfloat16* __restrict__ Ahi, const __nv_bfloat16* __restrict__ Alo,
    const __nv_bfloat16* __restrict__ Bhi, const __nv_bfloat16* __restrict__ Blo,
    size_t ldB,
    float* __restrict__ D, int ldD, const float* __restrict__ bias, uint32_t sm,
    char* smc, float* cps, float* cps2, int blin)
{
    int tid = threadIdx.x;
    int wid = tid >> 5, lane = tid & 31;
    int wm = wid >> 1, wn = wid & 1;

    float acc[2][8][4];
    #pragma unroll
    for (int i=0;i<2;i++) for (int j=0;j<8;j++) for (int q=0;q<4;q++) acc[i][j][q] = 0.f;

    auto load_chunk = [&](int kc) {
        uint32_t base = sm + (kc % 3)*STG;
        #pragma unroll
        for (int e = tid; e < 512; e += 256) {
            int row = e >> 2, c = e & 3;
            uint32_t off = OFF_NT(row, c);
            size_t gA = (size_t)row*256 + kc*32 + c*8;
            cp16(base         + off, Ahi + gA);
            cp16(base +  8192 + off, Alo + gA);
            int kr = e >> 4, c16 = e & 15;
            uint32_t offb = OFF_T(kr, c16);
            size_t gB = (size_t)(kc*32 + kr)*ldB + c16*8;
            cp16(base + 16384 + offb, Bhi + gB);
            cp16(base + 24576 + offb, Blo + gB);
        }
        CP_COMMIT();
    };

    load_chunk(0); load_chunk(1); load_chunk(2);

    #pragma unroll 1
    for (int kc = 0; kc < 8; kc++) {
        if (kc < 6)      asm volatile("cp.async.wait_group 2;" ::: "memory");
        else if (kc == 6) asm volatile("cp.async.wait_group 1;" ::: "memory");
        else             asm volatile("cp.async.wait_group 0;" ::: "memory");
        __syncthreads();

        uint32_t base = sm + (kc % 3)*STG;
        uint32_t sAhi = base, sAlo = base + 8192, sBhi = base + 16384, sBlo = base + 24576;

        #pragma unroll
        for (int ks = 0; ks < 2; ks++) {
            int c = ks*2 + (lane >> 4);
            uint32_t a_h[2][4], a_l[2][4];
            #pragma unroll
            for (int mi = 0; mi < 2; mi++) {
                int row = wm*32 + mi*16 + (lane & 15);
                uint32_t off = OFF_NT(row, c);
                ldsm_x4(a_h[mi][0], a_h[mi][1], a_h[mi][2], a_h[mi][3], sAhi + off);
                ldsm_x4(a_l[mi][0], a_l[mi][1], a_l[mi][2], a_l[mi][3], sAlo + off);
            }
            int kr = ks*16 + (lane & 7) + ((lane >> 3) & 1)*8;
            uint32_t b[4][4];
            #pragma unroll
            for (int nj = 0; nj < 4; nj++) {
                int n = wn*64 + nj*16 + ((lane >> 4) & 1)*8;
                uint32_t off = OFF_T(kr, (n >> 3));
                ldsm_x4_t(b[nj][0], b[nj][1], b[nj][2], b[nj][3], sBhi + off);
            }
            #pragma unroll
            for (int mi = 0; mi < 2; mi++)
                #pragma unroll
                for (int nj = 0; nj < 4; nj++) {
                    mma16816(acc[mi][nj*2],   a_h[mi], b[nj][0], b[nj][1]);
                    mma16816(acc[mi][nj*2+1], a_h[mi], b[nj][2], b[nj][3]);
                }
            #pragma unroll
            for (int mi = 0; mi < 2; mi++)
                #pragma unroll
                for (int nj = 0; nj < 4; nj++) {
                    mma16816(acc[mi][nj*2],   a_l[mi], b[nj][0], b[nj][1]);
                    mma16816(acc[mi][nj*2+1], a_l[mi], b[nj][2], b[nj][3]);
                }
            #pragma unroll
            for (int nj = 0; nj < 4; nj++) {
                int n = wn*64 + nj*16 + ((lane >> 4) & 1)*8;
                uint32_t off = OFF_T(kr, (n >> 3));
                ldsm_x4_t(b[nj][0], b[nj][1], b[nj][2], b[nj][3], sBlo + off);
            }
            #pragma unroll
            for (int mi = 0; mi < 2; mi++)
                #pragma unroll
                for (int nj = 0; nj < 4; nj++) {
                    mma16816(acc[mi][nj*2],   a_h[mi], b[nj][0], b[nj][1]);
                    mma16816(acc[mi][nj*2+1], a_h[mi], b[nj][2], b[nj][3]);
                }
        }
        __syncthreads();
        if (kc + 3 < 8) load_chunk(kc + 3);
    }

    int g = lane >> 2, tg = lane & 3;
    int slot = wn*4 + tg;
    float* srow  = (float*)smc;          // [128][8]
    float* srow2 = srow + 1024;          // [128][8]
    float* rtot  = srow + 2048;          // [128]
    float* rtot2 = srow + 2176;          // [128]
    #pragma unroll
    for (int mi = 0; mi < 2; mi++) {
        int r0 = wm*32 + mi*16 + g;
        float bv0 = bias[r0], bv1 = bias[r0+8];
        float s0=0.f, q0=0.f, s1=0.f, q1=0.f;
        #pragma unroll
        for (int nt = 0; nt < 8; nt++) {
            int col = wn*64 + nt*8 + tg*2;
            float v0 = acc[mi][nt][0] + bv0, v1 = acc[mi][nt][1] + bv0;
            float v2 = acc[mi][nt][2] + bv1, v3 = acc[mi][nt][3] + bv1;
            *(float2*)&D[(size_t)r0*ldD + col]     = make_float2(v0, v1);
            *(float2*)&D[(size_t)(r0+8)*ldD + col] = make_float2(v2, v3);
            s0 += v0 + v1; q0 += v0*v0 + v1*v1;
            s1 += v2 + v3; q1 += v2*v2 + v3*v3;
        }
        srow [r0*8 + slot] = s0;  srow2[r0*8 + slot] = q0;
        srow [(r0+8)*8 + slot] = s1;  srow2[(r0+8)*8 + slot] = q1;
    }
    __syncthreads();
    if (tid < 128) {
        float s=0.f, q=0.f;
        #pragma unroll
        for (int j = 0; j < 8; j++) { s += srow[tid*8+j]; q += srow2[tid*8+j]; }
        rtot[tid] = s; rtot2[tid] = q;
    }
    __syncthreads();
    if (tid < 16) {
        float s=0.f, q=0.f;
        #pragma unroll
        for (int j = 0; j < 8; j++) { s += rtot[tid*8+j]; q += rtot2[tid*8+j]; }
        cps [blin*16 + tid] = s;
        cps2[blin*16 + tid] = q;
    }
}

// ============================================================
// Stage 1: rfft(512) per row via packed radix-4 256-pt FFT.
// ============================================================
__global__ void __launch_bounds__(512) k_fft_fwd(const float* __restrict__ x) {
    __shared__ float sre[16*288];
    __shared__ float sim[16*288];
    __shared__ float2 tw[256];          // e^{-2pi i t/256}
    __shared__ float uer[129], uei[129];
    int tid = threadIdx.x;
    if (tid < 256) { float s,c; sincosf(6.283185307179586f*(float)tid/256.0f,&s,&c); tw[tid]=make_float2(c,-s); }
    if (tid < 129) { float s,c; sincosf(-6.283185307179586f*(float)tid/512.0f,&s,&c); uer[tid]=c; uei[tid]=s; }
    __syncthreads();
    int w = tid >> 5, lane = tid & 31;
    float* re = sre + w*288;
    float* im = sim + w*288;
    int row = blockIdx.x*16 + w;
    const float4* xr4 = (const float4*)(x + (size_t)row*512);
    #pragma unroll
    for (int j = 0; j < 4; j++) {
        float4 v = xr4[lane + 32*j];
        int f  = lane + 32*j;
        int r0 = __brev(2*f)   >> 24;
        int r1 = __brev(2*f+1) >> 24;
        re[SWF(r0)]=v.x; im[SWF(r0)]=v.y;
        re[SWF(r1)]=v.z; im[SWF(r1)]=v.w;
    }
    __syncwarp();
    #pragma unroll
    for (int h = 0; h < 2; h++) {
        int p = 4*(lane + 32*h);
        int a = SWF(p);
        float4 vr = *(float4*)&re[a];
        float4 vi = *(float4*)&im[a];
        float t0r=vr.x,t0i=vi.x, t1r=vr.z,t1i=vi.z, t2r=vr.y,t2i=vi.y, t3r=vr.w,t3i=vi.w;
        float s0r=t0r+t2r, s0i=t0i+t2i, d0r=t0r-t2r, d0i=t0i-t2i;
        float s1r=t1r+t3r, s1i=t1i+t3i, d1r=t1r-t3r, d1i=t1i-t3i;
        float4 yr, yi;
        yr.x = s0r+s1r; yi.x = s0i+s1i;
        yr.y = d0r+d1i; yi.y = d0i-d1r;
        yr.z = s0r-s1r; yi.z = s0i-s1i;
        yr.w = d0r-d1i; yi.w = d0i+d1r;
        *(float4*)&re[a] = yr; *(float4*)&im[a] = yi;
    }
    __syncwarp();
    #pragma unroll
    for (int rq = 0; rq < 3; rq++) {
        int Q = 4 << (2*rq);
        int step = 16 >> (2*rq);
        #pragma unroll
        for (int h = 0; h < 2; h++) {
            int b = lane + 32*h;
            int j = b & (Q-1);
            int p = ((b & ~(Q-1)) << 2) + j;
            float2 w1 = tw[(j*step) & 255];
            float2 w2 = tw[(2*j*step) & 255];
            float2 w3 = tw[(3*j*step) & 255];
            int a0 = SWF(p), a1 = SWF(p+2*Q), a2 = SWF(p+Q), a3 = SWF(p+3*Q);
            float x0r=re[a0], x0i=im[a0];
            float x1r=re[a1], x1i=im[a1];
            float x2r=re[a2], x2i=im[a2];
            float x3r=re[a3], x3i=im[a3];
            float t1r = x1r*w1.x - x1i*w1.y, t1i = x1r*w1.y + x1i*w1.x;
            float t2r = x2r*w2.x - x2i*w2.y, t2i = x2r*w2.y + x2i*w2.x;
            float t3r = x3r*w3.x - x3i*w3.y, t3i = x3r*w3.y + x3i*w3.x;
            float s0r=x0r+t2r, s0i=x0i+t2i, d0r=x0r-t2r, d0i=x0i-t2i;
            float s1r=t1r+t3r, s1i=t1i+t3i, d1r=t1r-t3r, d1i=t1i-t3i;
            re[a0]=s0r+s1r; im[a0]=s0i+s1i;
            re[a2]=d0r+d1i; im[a2]=d0i-d1r;
            re[a1]=s0r-s1r; im[a1]=s0i-s1i;
            re[a3]=d0r-d1i; im[a3]=d0i+d1r;
        }
        __syncwarp();
    }
    const float SC = 0.012271846303085129f;  // 2*pi/512
    float ro[5], io[5];
    #pragma unroll
    for (int j = 0; j < 5; j++) {
        int k = lane + 32*j;
        if (k <= 128) {
            int km = (256-k) & 255;
            float zr=re[SWF(k)],  zi= im[SWF(k)];
            float mr=re[SWF(km)], mi=-im[SWF(km)];
            float er=0.5f*(zr+mr), ei=0.5f*(zi+mi);
            float dr=0.5f*(zr-mr), di=0.5f*(zi-mi);
            float pr=di, pi=-dr;
            float wr=uer[k], wi=uei[k];
            float qr=pr*wr-pi*wi, qi=pr*wi+pi*wr;
            ro[j] = (er+qr)*SC;
            io[j] = (ei+qi)*SC;
        }
    }
    __syncthreads();
    float* ore = sre;   // reuse: [129][16]
    float* oim = sim;
    #pragma unroll
    for (int j = 0; j < 5; j++) {
        int k = lane + 32*j;
        if (k <= 128) { ore[k*16+w] = ro[j]; oim[k*16+w] = io[j]; }
    }
    __syncthreads();
    int base = blockIdx.x*16;
    for (int idx = tid; idx < 129*8; idx += 512) {
        int m = idx >> 3, rr = (idx & 7) << 1;
        size_t o = (size_t)m*ROWS1 + base + rr;
        __nv_bfloat16 h0,l0,h1,l1;
        __nv_bfloat162 v;
        split2(ore[m*16+rr], h0, l0); split2(ore[m*16+rr+1], h1, l1);
        v.x=h0; v.y=h1; *(__nv_bfloat162*)&d_Xr_hi[o] = v;
        v.x=l0; v.y=l1; *(__nv_bfloat162*)&d_Xr_lo[o] = v;
        split2(oim[m*16+rr], h0, l0); split2(oim[m*16+rr+1], h1, l1);
        v.x=h0; v.y=h1; *(__nv_bfloat162*)&d_Xi_hi[o] = v;
        v.x=l0; v.y=l1; *(__nv_bfloat162*)&d_Xi_lo[o] = v;
    }
}

// ============================================================
// Stage 2a: split wmat + pct into bf16 hi/lo
// ============================================================
__global__ void k_wpsplit(const float* __restrict__ wmat, const float* __restrict__ pct) {
    int i = blockIdx.x*256 + threadIdx.x;
    __nv_bfloat16 h, l;
    if (i < MMAX*LMAX*HHI) { split2(wmat[i], h, l); d_Wm_hi[i]=h; d_Wm_lo[i]=l; }
    if (i < MMAX*LMAX*HLO) { split2(pct[i],  h, l); d_P_hi[i]=h;  d_P_lo[i]=l; }
}

// ============================================================
// Stage 2b: split conv weights to bf16 hi/lo
// ============================================================
__global__ void k_wsplit(const float* __restrict__ w) {
    int i = blockIdx.x*256 + threadIdx.x;   // 65536 total
    __nv_bfloat16 h, l;
    split2(w[i], h, l);
    d_Whi[i] = h; d_Wlo[i] = l;
}

// ============================================================
// Stage 2c: At[m][klo][kh] = sum_l P[l][klo] W[l][kh] via mma (both trans).
// M=klo 128, N=kh 128 per block (grid 2 x MMAX), K=l 128.
// ============================================================
__global__ void __launch_bounds__(256) k_buildA_mma() {
    extern __shared__ __align__(128) char dsm[];
    uint32_t sm = smem_u32(dsm);
    int tid = threadIdx.x;
    int wid = tid >> 5, lane = tid & 31;
    int wm = wid >> 1, wn = wid & 1;
    int m = blockIdx.y, kh0 = blockIdx.x * 128;

    const __nv_bfloat16* Ph = d_P_hi  + (size_t)m*LMAX*HLO;        // [l][klo]
    const __nv_bfloat16* Pl = d_P_lo  + (size_t)m*LMAX*HLO;
    const __nv_bfloat16* Wh = d_Wm_hi + (size_t)m*LMAX*HHI + kh0;  // [l][kh]
    const __nv_bfloat16* Wl = d_Wm_lo + (size_t)m*LMAX*HHI + kh0;

    float acc[2][8][4];
    #pragma unroll
    for (int i=0;i<2;i++) for (int j=0;j<8;j++) for (int q=0;q<4;q++) acc[i][j][q] = 0.f;

    auto load_chunk = [&](int kc) {
        uint32_t base = sm + (kc % 3)*STG;
        #pragma unroll
        for (int e = tid; e < 512; e += 256) {
            int kr = e >> 4, c16 = e & 15;
            uint32_t off = OFF_T(kr, c16);
            size_t gP = (size_t)(kc*32 + kr)*HLO + c16*8;
            size_t gW = (size_t)(kc*32 + kr)*HHI + c16*8;
            cp16(base         + off, Ph + gP);
            cp16(base +  8192 + off, Pl + gP);
            cp16(base + 16384 + off, Wh + gW);
            cp16(base + 24576 + off, Wl + gW);
        }
        CP_COMMIT();
    };

    load_chunk(0); load_chunk(1); load_chunk(2);

    #pragma unroll 1
    for (int kc = 0; kc < 4; kc++) {
        if (kc < 2)      asm volatile("cp.async.wait_group 2;" ::: "memory");
        else if (kc == 2) asm volatile("cp.async.wait_group 1;" ::: "memory");
        else             asm volatile("cp.async.wait_group 0;" ::: "memory");
        __syncthreads();

        uint32_t base = sm + (kc % 3)*STG;
        uint32_t sPh = base, sPl = base + 8192, sWh = base + 16384, sWl = base + 24576;

        #pragma unroll
        for (int ks = 0; ks < 2; ks++) {
            int kr = ks*16 + (lane & 7) + ((lane >> 3) & 1)*8;
            // A = P^T: trans load, frag order {r0, r2, r1, r3}
            uint32_t a_h[2][4], a_l[2][4];
            #pragma unroll
            for (int mi = 0; mi < 2; mi++) {
                int mcol = wm*4 + mi*2 + ((lane >> 4) & 1);
                uint32_t off = OFF_T(kr, mcol);
                uint32_t r0,r1,r2,r3;
                ldsm_x4_t(r0, r1, r2, r3, sPh + off);
                a_h[mi][0]=r0; a_h[mi][1]=r2; a_h[mi][2]=r1; a_h[mi][3]=r3;
                ldsm_x4_t(r0, r1, r2, r3, sPl + off);
                a_l[mi][0]=r0; a_l[mi][1]=r2; a_l[mi][2]=r1; a_l[mi][3]=r3;
            }
            uint32_t b[4][4];
            #pragma unroll
            for (int nj = 0; nj < 4; nj++) {
                int n = wn*64 + nj*16 + ((lane >> 4) & 1)*8;
                uint32_t off = OFF_T(kr, (n >> 3));
                ldsm_x4_t(b[nj][0], b[nj][1], b[nj][2], b[nj][3], sWh + off);
            }
            #pragma unroll
            for (int mi = 0; mi < 2; mi++)
                #pragma unroll
                for (int nj = 0; nj < 4; nj++) {
                    mma16816(acc[mi][nj*2],   a_h[mi], b[nj][0], b[nj][1]);
                    mma16816(acc[mi][nj*2+1], a_h[mi], b[nj][2], b[nj][3]);
                }
            #pragma unroll
            for (int mi = 0; mi < 2; mi++)
                #pragma unroll
                for (int nj = 0; nj < 4; nj++) {
                    mma16816(acc[mi][nj*2],   a_l[mi], b[nj][0], b[nj][1]);
                    mma16816(acc[mi][nj*2+1], a_l[mi], b[nj][2], b[nj][3]);
                }
            #pragma unroll
            for (int nj = 0; nj < 4; nj++) {
                int n = wn*64 + nj*16 + ((lane >> 4) & 1)*8;
                uint32_t off = OFF_T(kr, (n >> 3));
                ldsm_x4_t(b[nj][0], b[nj][1], b[nj][2], b[nj][3], sWl + off);
            }
            #pragma unroll
            for (int mi = 0; mi < 2; mi++)
                #pragma unroll
                for (int nj = 0; nj < 4; nj++) {
                    mma16816(acc[mi][nj*2],   a_h[mi], b[nj][0], b[nj][1]);
                    mma16816(acc[mi][nj*2+1], a_h[mi], b[nj][2], b[nj][3]);
                }
        }
        __syncthreads();
        if (kc + 3 < 4) load_chunk(kc + 3);
    }

    int g = lane >> 2, tg = lane & 3;
    size_t Abase = (size_t)m*(HLO*HHI);
    #pragma unroll
    for (int mi = 0; mi < 2; mi++) {
        #pragma unroll
        for (int half = 0; half < 2; half++) {
            int r = wm*32 + mi*16 + g + half*8;
            #pragma unroll
            for (int nt = 0; nt < 8; nt++) {
                int col = kh0 + wn*64 + nt*8 + tg*2;
                float v0 = acc[mi][nt][half*2], v1 = acc[mi][nt][half*2+1];
                __nv_bfloat16 h0,l0,h1,l1;
                split2(v0, h0, l0); split2(v1, h1, l1);
                __nv_bfloat162 vh; vh.x=h0; vh.y=h1;
                __nv_bfloat162 vl; vl.x=l0; vl.y=l1;
                *(__nv_bfloat162*)&d_At_hi[Abase + (size_t)r*HHI + col] = vh;
                *(__nv_bfloat162*)&d_At_lo[Abase + (size_t)r*HHI + col] = vl;
            }
        }
    }
}

// ============================================================
// Stage 3: Legendre per-m GEMM.
// ============================================================
__global__ void __launch_bounds__(256) k_legendre_mma() {
    extern __shared__ __align__(128) char dsm[];
    int m = blockIdx.y;
    int bx = blockIdx.x;
    int half = bx >> 2;
    int bc0  = (bx & 3) * 128;
    size_t xo = (size_t)m*ROWS1 + (size_t)bc0*HHI;
    const __nv_bfloat16 *Ah, *Al;
    float* D;
    if (half) { Ah = d_Xi_hi + xo; Al = d_Xi_lo + xo; D = d_Gi; }
    else      { Ah = d_Xr_hi + xo; Al = d_Xr_lo + xo; D = d_Gr; }
    D += (size_t)m*ROWS2 + (size_t)bc0*HLO;
    const __nv_bfloat16* Bh = d_At_hi + (size_t)m*(HLO*HHI);
    const __nv_bfloat16* Bl = d_At_lo + (size_t)m*(HLO*HHI);
    gemm_nn(Ah, Al, Bh, Bl, D, HLO, smem_u32(dsm));
}

// ============================================================
// Stage 4: irfft(n=256)*256 per row via packed radix-4 128-pt inverse FFT.
// ============================================================
__global__ void k_ifft() {
    __shared__ float gre[129*8], gim[129*8];
    __shared__ float sre[8*144], sim[8*144];
    __shared__ float2 tw2[128];
    __shared__ float wqr[128], wqi[128];
    int tid = threadIdx.x;
    if (tid < 128){ float s,c; sincosf(6.283185307179586f*(float)tid/128.f,&s,&c); tw2[tid]=make_float2(c,s); }
    if (tid < 128){ float s,c; sincosf(6.283185307179586f*(float)tid/256.f,&s,&c); wqr[tid]=c; wqi[tid]=s; }
    int base = blockIdx.x*8;
    for (int idx = tid; idx < 129*8; idx += 256) {
        int m = idx >> 3, r = idx & 7;
        gre[idx] = d_Gr[m*ROWS2 + base + r];
        gim[idx] = d_Gi[m*ROWS2 + base + r];
    }
    __syncthreads();
    int w = tid >> 5, lane = tid & 31;
    float* re = sre + w*144;
    float* im = sim + w*144;
    #pragma unroll 4
    for (int k = lane; k < 128; k += 32) {
        float ar = gre[k*8+w],        ai =  gim[k*8+w];
        float br = gre[(128-k)*8+w],  bi = -gim[(128-k)*8+w];
        float wr = wqr[k], wi = wqi[k];
        float c1r = 1.f - wi, c1i =  wr;
        float c2r = 1.f + wi, c2i = -wr;
        float Zr = ar*c1r - ai*c1i + br*c2r - bi*c2i;
        float Zi = ar*c1i + ai*c1r + br*c2i + bi*c2r;
        int rv = __brev(k) >> 25;
        re[SWF(rv)] = Zr; im[SWF(rv)] = Zi;
    }
    __syncwarp();
    {
        int p = 4*lane;
        int a = SWF(p);
        float4 vr = *(float4*)&re[a];
        float4 vi = *(float4*)&im[a];
        float t0r=vr.x,t0i=vi.x, t1r=vr.z,t1i=vi.z, t2r=vr.y,t2i=vi.y, t3r=vr.w,t3i=vi.w;
        float s0r=t0r+t2r, s0i=t0i+t2i, d0r=t0r-t2r, d0i=t0i-t2i;
        float s1r=t1r+t3r, s1i=t1i+t3i, d1r=t1r-t3r, d1i=t1i-t3i;
        float4 yr, yi;
        yr.x = s0r+s1r; yi.x = s0i+s1i;
        yr.y = d0r-d1i; yi.y = d0i+d1r;
        yr.z = s0r-s1r; yi.z = s0i-s1i;
        yr.w = d0r+d1i; yi.w = d0i-d1r;
        *(float4*)&re[a] = yr; *(float4*)&im[a] = yi;
    }
    __syncwarp();
    #pragma unroll
    for (int rq = 0; rq < 2; rq++) {
        int Q = 4 << (2*rq);
        int step = 8 >> (2*rq);
        int b = lane;
        int j = b & (Q-1);
        int p = ((b & ~(Q-1)) << 2) + j;
        float2 w1 = tw2[(j*step) & 127];
        float2 w2 = tw2[(2*j*step) & 127];
        float2 w3 = tw2[(3*j*step) & 127];
        int a0 = SWF(p), a1 = SWF(p+2*Q), a2 = SWF(p+Q), a3 = SWF(p+3*Q);
        float x0r=re[a0], x0i=im[a0];
        float x1r=re[a1], x1i=im[a1];
        float x2r=re[a2], x2i=im[a2];
        float x3r=re[a3], x3i=im[a3];
        float t1r = x1r*w1.x - x1i*w1.y, t1i = x1r*w1.y + x1i*w1.x;
        float t2r = x2r*w2.x - x2i*w2.y, t2i = x2r*w2.y + x2i*w2.x;
        float t3r = x3r*w3.x - x3i*w3.y, t3i = x3r*w3.y + x3i*w3.x;
        float s0r=x0r+t2r, s0i=x0i+t2i, d0r=x0r-t2r, d0i=x0i-t2i;
        float s1r=t1r+t3r, s1i=t1i+t3i, d1r=t1r-t3r, d1i=t1i-t3i;
        re[a0]=s0r+s1r; im[a0]=s0i+s1i;
        re[a2]=d0r-d1i; im[a2]=d0i+d1r;
        re[a1]=s0r-s1r; im[a1]=s0i-s1i;
        re[a3]=d0r+d1i; im[a3]=d0i-d1r;
        __syncwarp();
    }
    #pragma unroll
    for (int h = 0; h < 2; h++) {
        int p = lane + 32*h;
        float2 wv = tw2[p];
        int a0 = SWF(p), a1 = SWF(p+64);
        float x0r=re[a0], x0i=im[a0];
        float x1r=re[a1], x1i=im[a1];
        float tr = x1r*wv.x - x1i*wv.y, ti = x1r*wv.y + x1i*wv.x;
        re[a0]=x0r+tr; im[a0]=x0i+ti;
        re[a1]=x0r-tr; im[a1]=x0i-ti;
    }
    __syncwarp();
    __nv_bfloat162* yh = (__nv_bfloat162*)d_Yc_hi + (size_t)(base + w)*128;
    __nv_bfloat162* yl = (__nv_bfloat162*)d_Yc_lo + (size_t)(base + w)*128;
    #pragma unroll 4
    for (int n = lane; n < 128; n += 32) {
        __nv_bfloat16 h0,l0,h1,l1;
        split2(re[SWF(n)], h0, l0);
        split2(im[SWF(n)], h1, l1);
        __nv_bfloat162 vh; vh.x=h0; vh.y=h1;
        __nv_bfloat162 vl; vl.x=l0; vl.y=l1;
        yh[n] = vh; yl[n] = vl;
    }
}

// ============================================================
// Stage 5: 1x1 conv + fused GN partial stats.
// ============================================================
__global__ void __launch_bounds__(256) k_conv_mma(const float* __restrict__ bias) {
    extern __shared__ __align__(128) char dsm[];
    int b = blockIdx.z, o0 = blockIdx.y*128, hw0 = blockIdx.x*128;
    int blin = (b*2 + blockIdx.y)*256 + blockIdx.x;
    const __nv_bfloat16* Ah = d_Whi + (size_t)o0*CIN;
    const __nv_bfloat16* Al = d_Wlo + (size_t)o0*CIN;
    const __nv_bfloat16* Bh = d_Yc_hi + (size_t)b*CIN*HWLO + hw0;
    const __nv_bfloat16* Bl = d_Yc_lo + (size_t)b*CIN*HWLO + hw0;
    float* D = d_H + ((size_t)b*COUT + o0)*HWLO + hw0;
    gemm_kn(Ah, Al, Bh, Bl, (size_t)HWLO, D, HWLO, bias + o0, smem_u32(dsm),
            dsm, d_cps, d_cps2, blin);
}

// ============================================================
// Stage 6: GroupNorm final stats from conv partials (deterministic).
// ============================================================
__global__ void k_gnfin() {
    int t = threadIdx.x;   // 64
    int b = t >> 5, g = t & 31;
    int y = g >> 4, gi = g & 15;
    int base = ((b*2 + y)*256)*16 + gi;
    double s = 0.0, s2 = 0.0;
    for (int bx = 0; bx < 256; bx++) {
        s  += (double)d_cps [base + bx*16];
        s2 += (double)d_cps2[base + bx*16];
    }
    const double N = (double)(CPG*HWLO);
    double mean = s / N;
    double var  = s2 / N - mean*mean;
    d_mean[b*32+g] = (float)mean;
    d_rstd[b*32+g] = rsqrtf((float)var + 1e-5f);
}

// ============================================================
// Stage 7: normalize + affine + exact GELU
// ============================================================
__global__ void k_gnapply(const float* __restrict__ gamma, const float* __restrict__ beta,
                          float* __restrict__ out) {
    int idx = blockIdx.x*256 + threadIdx.x;
    int fidx = idx * 4;
    int o  = (fidx >> 15) & 255;
    int bg = fidx >> 18;
    float a  = gamma[o] * d_rstd[bg];
    float b2 = beta[o] - d_mean[bg] * a;
    float4 h = ((const float4*)d_H)[idx];
    float v0 = h.x*a + b2, v1 = h.y*a + b2, v2 = h.z*a + b2, v3 = h.w*a + b2;
    float4 r;
    r.x = v0 * normcdff(v0);
    r.y = v1 * normcdff(v1);
    r.z = v2 * normcdff(v2);
    r.w = v3 * normcdff(v3);
    ((float4*)out)[idx] = r;
}

// ============================================================
extern "C" void kernel_launch(void* const* d_in, const int* in_sizes, int n_in,
                              void* d_out, int out_size) {
    const float* x      = (const float*)d_in[0];
    const float* conv_w = (const float*)d_in[1];
    const float* conv_b = (const float*)d_in[2];
    const float* gamma  = (const float*)d_in[3];
    const float* beta   = (const float*)d_in[4];
    const float* wmat   = (const float*)d_in[5];
    const float* pct    = (const float*)d_in[6];
    float* out = (float*)d_out;

    cudaFuncSetAttribute(k_buildA_mma,   cudaFuncAttributeMaxDynamicSharedMemorySize, GEMM_SMEM);
    cudaFuncSetAttribute(k_legendre_mma, cudaFuncAttributeMaxDynamicSharedMemorySize, GEMM_SMEM);
    cudaFuncSetAttribute(k_conv_mma,     cudaFuncAttributeMaxDynamicSharedMemorySize, GEMM_SMEM);

    k_fft_fwd     <<<ROWS1/16, 512>>>(x);
    k_wpsplit     <<<(MMAX*LMAX*HHI+255)/256, 256>>>(wmat, pct);
    k_wsplit      <<<256, 256>>>(conv_w);
    k_buildA_mma  <<<dim3(2, MMAX), 256, GEMM_SMEM>>>();
    k_legendre_mma<<<dim3(8, MMAX), 256, GEMM_SMEM>>>();
    k_ifft        <<<ROWS2/8, 256>>>();
    k_conv_mma    <<<dim3(HWLO/128, COUT/128, BATCH), 256, GEMM_SMEM>>>(conv_b);
    k_gnfin       <<<1, 64>>>();
    k_gnapply     <<<(BC*HWLO)/4/256, 256>>>(gamma, beta, out);
}

// round 9
// speedup vs baseline: 1.5948x; 1.0295x over previous
#include <cuda_runtime.h>
#include <cuda_bf16.h>
#include <math.h>
#include <stdint.h>

#define BATCH 2
#define CIN 256
#define COUT 256
#define HHI 256
#define WHI 512
#define HLO 128
#define WLO 256
#define MMAX 129
#define LMAX 128
#define CPG 8
#define BC (BATCH*CIN)          /* 512    */
#define ROWS1 (BC*HHI)          /* 131072 */
#define ROWS2 (BC*HLO)          /* 65536  */
#define HWLO (HLO*WLO)          /* 32768  */

// -------- scratch (static device globals; no allocation allowed) --------
__device__ __align__(16) __nv_bfloat16 d_Xr_hi[MMAX*ROWS1];
__device__ __align__(16) __nv_bfloat16 d_Xr_lo[MMAX*ROWS1];
__device__ __align__(16) __nv_bfloat16 d_Xi_hi[MMAX*ROWS1];
__device__ __align__(16) __nv_bfloat16 d_Xi_lo[MMAX*ROWS1];
__device__ __align__(16) __nv_bfloat16 d_At_hi[MMAX*HLO*HHI];   // [m][klo][kh]
__device__ __align__(16) __nv_bfloat16 d_At_lo[MMAX*HLO*HHI];
__device__ __align__(16) __nv_bfloat16 d_Whi[COUT*CIN];
__device__ __align__(16) __nv_bfloat16 d_Wlo[COUT*CIN];
__device__ float d_Gr[MMAX*ROWS2];        // [m][bc*128+klo]
__device__ float d_Gi[MMAX*ROWS2];
__device__ __align__(16) __nv_bfloat16 d_Yc_hi[BC*HWLO];  // [b][c][hw]
__device__ __align__(16) __nv_bfloat16 d_Yc_lo[BC*HWLO];
__device__ float d_H [BC*HWLO];           // [b][o][hw]
__device__ float d_cps[1024*16], d_cps2[1024*16];
__device__ float d_mean[BATCH*32];
__device__ float d_rstd[BATCH*32];

// ======================= helpers =======================
__device__ __forceinline__ uint32_t smem_u32(const void* p) {
    uint32_t a;
    asm("{ .reg .u64 t; cvta.to.shared.u64 t, %1; cvt.u32.u64 %0, t; }" : "=r"(a) : "l"(p));
    return a;
}
__device__ __forceinline__ void ldsm_x4(uint32_t& r0, uint32_t& r1, uint32_t& r2, uint32_t& r3, uint32_t addr) {
    asm volatile("ldmatrix.sync.aligned.m8n8.x4.shared.b16 {%0,%1,%2,%3}, [%4];"
        : "=r"(r0), "=r"(r1), "=r"(r2), "=r"(r3) : "r"(addr));
}
__device__ __forceinline__ void ldsm_x4_t(uint32_t& r0, uint32_t& r1, uint32_t& r2, uint32_t& r3, uint32_t addr) {
    asm volatile("ldmatrix.sync.aligned.m8n8.x4.trans.shared.b16 {%0,%1,%2,%3}, [%4];"
        : "=r"(r0), "=r"(r1), "=r"(r2), "=r"(r3) : "r"(addr));
}
__device__ __forceinline__ void mma16816(float* d, const uint32_t* a, uint32_t b0, uint32_t b1) {
    asm volatile("mma.sync.aligned.m16n8k16.row.col.f32.bf16.bf16.f32 "
        "{%0,%1,%2,%3}, {%4,%5,%6,%7}, {%8,%9}, {%0,%1,%2,%3};"
        : "+f"(d[0]), "+f"(d[1]), "+f"(d[2]), "+f"(d[3])
        : "r"(a[0]), "r"(a[1]), "r"(a[2]), "r"(a[3]), "r"(b0), "r"(b1));
}
__device__ __forceinline__ void cp16(uint32_t dst, const void* src) {
    asm volatile("cp.async.cg.shared.global [%0], [%1], 16;" :: "r"(dst), "l"(src));
}
#define CP_COMMIT() asm volatile("cp.async.commit_group;" ::: "memory")
__device__ __forceinline__ void split2(float v, __nv_bfloat16& h, __nv_bfloat16& l) {
    h = __float2bfloat16(v);
    l = __float2bfloat16(v - __bfloat162float(h));
}

// stage layout: 4 tiles x 8KB = 32KB; 3 stages = 96KB
#define STG (32768)
#define GEMM_SMEM (3*STG)
#define BA_SMEM   (131072)

// non-trans tile [128 rows][32 k], 64B rows, swizzle c^((row>>1)&3)
#define OFF_NT(row, c) ((uint32_t)((row)<<6) + (uint32_t)(((c) ^ (((row)>>1)&3)) << 4))
// trans tile [32 k][128 n], 256B rows, swizzle c^(k&7)
#define OFF_T(k, c16)  ((uint32_t)((k)<<8) + (uint32_t)(((c16) ^ ((k)&7)) << 4))

// smem FFT pad
#define SWF(i) ((i) + ((((i)>>5))<<2))

// ============================================================
// GEMM core, both operands k-major: D[128m][128n] = A[128][256] B[128][256]^T
// ============================================================
__device__ __forceinline__ void gemm_nn(
    const __nv_bfloat16* __restrict__ Ahi, const __nv_bfloat16* __restrict__ Alo,
    const __nv_bfloat16* __restrict__ Bhi, const __nv_bfloat16* __restrict__ Blo,
    float* __restrict__ D, int ldD, uint32_t sm)
{
    int tid = threadIdx.x;
    int wid = tid >> 5, lane = tid & 31;
    int wm = wid >> 1, wn = wid & 1;

    float acc[2][8][4];
    #pragma unroll
    for (int i=0;i<2;i++) for (int j=0;j<8;j++) for (int q=0;q<4;q++) acc[i][j][q] = 0.f;

    auto load_chunk = [&](int kc) {
        uint32_t base = sm + (kc % 3)*STG;
        #pragma unroll
        for (int e = tid; e < 512; e += 256) {
            int row = e >> 2, c = e & 3;
            uint32_t off = OFF_NT(row, c);
            size_t g = (size_t)row*256 + kc*32 + c*8;
            cp16(base          + off, Ahi + g);
            cp16(base +  8192  + off, Alo + g);
            cp16(base + 16384  + off, Bhi + g);
            cp16(base + 24576  + off, Blo + g);
        }
        CP_COMMIT();
    };

    load_chunk(0); load_chunk(1); load_chunk(2);

    #pragma unroll 1
    for (int kc = 0; kc < 8; kc++) {
        if (kc < 6)      asm volatile("cp.async.wait_group 2;" ::: "memory");
        else if (kc == 6) asm volatile("cp.async.wait_group 1;" ::: "memory");
        else             asm volatile("cp.async.wait_group 0;" ::: "memory");
        __syncthreads();

        uint32_t base = sm + (kc % 3)*STG;
        uint32_t sAhi = base, sAlo = base + 8192, sBhi = base + 16384, sBlo = base + 24576;

        #pragma unroll
        for (int ks = 0; ks < 2; ks++) {
            int c = ks*2 + (lane >> 4);
            uint32_t a_h[2][4], a_l[2][4];
            #pragma unroll
            for (int mi = 0; mi < 2; mi++) {
                int row = wm*32 + mi*16 + (lane & 15);
                uint32_t off = OFF_NT(row, c);
                ldsm_x4(a_h[mi][0], a_h[mi][1], a_h[mi][2], a_h[mi][3], sAhi + off);
                ldsm_x4(a_l[mi][0], a_l[mi][1], a_l[mi][2], a_l[mi][3], sAlo + off);
            }
            uint32_t b[4][4];
            #pragma unroll
            for (int nj = 0; nj < 4; nj++) {
                int row = wn*64 + nj*16 + (lane & 7) + ((lane >> 3) & 1)*8;
                uint32_t off = OFF_NT(row, c);
                ldsm_x4(b[nj][0], b[nj][1], b[nj][2], b[nj][3], sBhi + off);
            }
            #pragma unroll
            for (int mi = 0; mi < 2; mi++)
                #pragma unroll
                for (int nj = 0; nj < 4; nj++) {
                    mma16816(acc[mi][nj*2],   a_h[mi], b[nj][0], b[nj][2]);
                    mma16816(acc[mi][nj*2+1], a_h[mi], b[nj][1], b[nj][3]);
                }
            #pragma unroll
            for (int mi = 0; mi < 2; mi++)
                #pragma unroll
                for (int nj = 0; nj < 4; nj++) {
                    mma16816(acc[mi][nj*2],   a_l[mi], b[nj][0], b[nj][2]);
                    mma16816(acc[mi][nj*2+1], a_l[mi], b[nj][1], b[nj][3]);
                }
            #pragma unroll
            for (int nj = 0; nj < 4; nj++) {
                int row = wn*64 + nj*16 + (lane & 7) + ((lane >> 3) & 1)*8;
                uint32_t off = OFF_NT(row, c);
                ldsm_x4(b[nj][0], b[nj][1], b[nj][2], b[nj][3], sBlo + off);
            }
            #pragma unroll
            for (int mi = 0; mi < 2; mi++)
                #pragma unroll
                for (int nj = 0; nj < 4; nj++) {
                    mma16816(acc[mi][nj*2],   a_h[mi], b[nj][0], b[nj][2]);
                    mma16816(acc[mi][nj*2+1], a_h[mi], b[nj][1], b[nj][3]);
                }
        }
        __syncthreads();
        if (kc + 3 < 8) load_chunk(kc + 3);
    }

    int g = lane >> 2, tg = lane & 3;
    #pragma unroll
    for (int mi = 0; mi < 2; mi++) {
        int r0 = wm*32 + mi*16 + g;
        #pragma unroll
        for (int nt = 0; nt < 8; nt++) {
            int col = wn*64 + nt*8 + tg*2;
            *(float2*)&D[(size_t)r0*ldD + col]     = make_float2(acc[mi][nt][0], acc[mi][nt][1]);
            *(float2*)&D[(size_t)(r0+8)*ldD + col] = make_float2(acc[mi][nt][2], acc[mi][nt][3]);
        }
    }
}

// ============================================================
// GEMM core, A k-major [128 m][256 k], B row-major [256 k][N] (ldB stride).
// Fused GroupNorm partial stats.
// ============================================================
__device__ __forceinline__ void gemm_kn(
    const __nv_bfloat16* __restrict__ Ahi, const __nv_bfloat16* __restrict__ Alo,
    const __nv_bfloat16* __restrict__ Bhi, const __nv_bfloat16* __restrict__ Blo,
    size_t ldB,
    float* __restrict__ D, int ldD, const float* __restrict__ bias, uint32_t sm,
    char* smc, float* cps, float* cps2, int blin)
{
    int tid = threadIdx.x;
    int wid = tid >> 5, lane = tid & 31;
    int wm = wid >> 1, wn = wid & 1;

    float acc[2][8][4];
    #pragma unroll
    for (int i=0;i<2;i++) for (int j=0;j<8;j++) for (int q=0;q<4;q++) acc[i][j][q] = 0.f;

    auto load_chunk = [&](int kc) {
        uint32_t base = sm + (kc % 3)*STG;
        #pragma unroll
        for (int e = tid; e < 512; e += 256) {
            int row = e >> 2, c = e & 3;
            uint32_t off = OFF_NT(row, c);
            size_t gA = (size_t)row*256 + kc*32 + c*8;
            cp16(base         + off, Ahi + gA);
            cp16(base +  8192 + off, Alo + gA);
            int kr = e >> 4, c16 = e & 15;
            uint32_t offb = OFF_T(kr, c16);
            size_t gB = (size_t)(kc*32 + kr)*ldB + c16*8;
            cp16(base + 16384 + offb, Bhi + gB);
            cp16(base + 24576 + offb, Blo + gB);
        }
        CP_COMMIT();
    };

    load_chunk(0); load_chunk(1); load_chunk(2);

    #pragma unroll 1
    for (int kc = 0; kc < 8; kc++) {
        if (kc < 6)      asm volatile("cp.async.wait_group 2;" ::: "memory");
        else if (kc == 6) asm volatile("cp.async.wait_group 1;" ::: "memory");
        else             asm volatile("cp.async.wait_group 0;" ::: "memory");
        __syncthreads();

        uint32_t base = sm + (kc % 3)*STG;
        uint32_t sAhi = base, sAlo = base + 8192, sBhi = base + 16384, sBlo = base + 24576;

        #pragma unroll
        for (int ks = 0; ks < 2; ks++) {
            int c = ks*2 + (lane >> 4);
            uint32_t a_h[2][4], a_l[2][4];
            #pragma unroll
            for (int mi = 0; mi < 2; mi++) {
                int row = wm*32 + mi*16 + (lane & 15);
                uint32_t off = OFF_NT(row, c);
                ldsm_x4(a_h[mi][0], a_h[mi][1], a_h[mi][2], a_h[mi][3], sAhi + off);
                ldsm_x4(a_l[mi][0], a_l[mi][1], a_l[mi][2], a_l[mi][3], sAlo + off);
            }
            int kr = ks*16 + (lane & 7) + ((lane >> 3) & 1)*8;
            uint32_t b[4][4];
            #pragma unroll
            for (int nj = 0; nj < 4; nj++) {
                int n = wn*64 + nj*16 + ((lane >> 4) & 1)*8;
                uint32_t off = OFF_T(kr, (n >> 3));
                ldsm_x4_t(b[nj][0], b[nj][1], b[nj][2], b[nj][3], sBhi + off);
            }
            #pragma unroll
            for (int mi = 0; mi < 2; mi++)
                #pragma unroll
                for (int nj = 0; nj < 4; nj++) {
                    mma16816(acc[mi][nj*2],   a_h[mi], b[nj][0], b[nj][1]);
                    mma16816(acc[mi][nj*2+1], a_h[mi], b[nj][2], b[nj][3]);
                }
            #pragma unroll
            for (int mi = 0; mi < 2; mi++)
                #pragma unroll
                for (int nj = 0; nj < 4; nj++) {
                    mma16816(acc[mi][nj*2],   a_l[mi], b[nj][0], b[nj][1]);
                    mma16816(acc[mi][nj*2+1], a_l[mi], b[nj][2], b[nj][3]);
                }
            #pragma unroll
            for (int nj = 0; nj < 4; nj++) {
                int n = wn*64 + nj*16 + ((lane >> 4) & 1)*8;
                uint32_t off = OFF_T(kr, (n >> 3));
                ldsm_x4_t(b[nj][0], b[nj][1], b[nj][2], b[nj][3], sBlo + off);
            }
            #pragma unroll
            for (int mi = 0; mi < 2; mi++)
                #pragma unroll
                for (int nj = 0; nj < 4; nj++) {
                    mma16816(acc[mi][nj*2],   a_h[mi], b[nj][0], b[nj][1]);
                    mma16816(acc[mi][nj*2+1], a_h[mi], b[nj][2], b[nj][3]);
                }
        }
        __syncthreads();
        if (kc + 3 < 8) load_chunk(kc + 3);
    }

    int g = lane >> 2, tg = lane & 3;
    int slot = wn*4 + tg;
    float* srow  = (float*)smc;          // [128][8]
    float* srow2 = srow + 1024;          // [128][8]
    float* rtot  = srow + 2048;          // [128]
    float* rtot2 = srow + 2176;          // [128]
    #pragma unroll
    for (int mi = 0; mi < 2; mi++) {
        int r0 = wm*32 + mi*16 + g;
        float bv0 = bias[r0], bv1 = bias[r0+8];
        float s0=0.f, q0=0.f, s1=0.f, q1=0.f;
        #pragma unroll
        for (int nt = 0; nt < 8; nt++) {
            int col = wn*64 + nt*8 + tg*2;
            float v0 = acc[mi][nt][0] + bv0, v1 = acc[mi][nt][1] + bv0;
            float v2 = acc[mi][nt][2] + bv1, v3 = acc[mi][nt][3] + bv1;
            *(float2*)&D[(size_t)r0*ldD + col]     = make_float2(v0, v1);
            *(float2*)&D[(size_t)(r0+8)*ldD + col] = make_float2(v2, v3);
            s0 += v0 + v1; q0 += v0*v0 + v1*v1;
            s1 += v2 + v3; q1 += v2*v2 + v3*v3;
        }
        srow [r0*8 + slot] = s0;  srow2[r0*8 + slot] = q0;
        srow [(r0+8)*8 + slot] = s1;  srow2[(r0+8)*8 + slot] = q1;
    }
    __syncthreads();
    if (tid < 128) {
        float s=0.f, q=0.f;
        #pragma unroll
        for (int j = 0; j < 8; j++) { s += srow[tid*8+j]; q += srow2[tid*8+j]; }
        rtot[tid] = s; rtot2[tid] = q;
    }
    __syncthreads();
    if (tid < 16) {
        float s=0.f, q=0.f;
        #pragma unroll
        for (int j = 0; j < 8; j++) { s += rtot[tid*8+j]; q += rtot2[tid*8+j]; }
        cps [blin*16 + tid] = s;
        cps2[blin*16 + tid] = q;
    }
}

// ============================================================
// Stage 1: rfft(512) per row via packed radix-4 256-pt FFT.
// ============================================================
__global__ void __launch_bounds__(512) k_fft_fwd(const float* __restrict__ x) {
    __shared__ float sre[16*288];
    __shared__ float sim[16*288];
    __shared__ float2 tw[256];          // e^{-2pi i t/256}
    __shared__ float uer[129], uei[129];
    int tid = threadIdx.x;
    if (tid < 256) { float s,c; sincosf(6.283185307179586f*(float)tid/256.0f,&s,&c); tw[tid]=make_float2(c,-s); }
    if (tid < 129) { float s,c; sincosf(-6.283185307179586f*(float)tid/512.0f,&s,&c); uer[tid]=c; uei[tid]=s; }
    __syncthreads();
    int w = tid >> 5, lane = tid & 31;
    float* re = sre + w*288;
    float* im = sim + w*288;
    int row = blockIdx.x*16 + w;
    const float4* xr4 = (const float4*)(x + (size_t)row*512);
    #pragma unroll
    for (int j = 0; j < 4; j++) {
        float4 v = xr4[lane + 32*j];
        int f  = lane + 32*j;
        int r0 = __brev(2*f)   >> 24;
        int r1 = __brev(2*f+1) >> 24;
        re[SWF(r0)]=v.x; im[SWF(r0)]=v.y;
        re[SWF(r1)]=v.z; im[SWF(r1)]=v.w;
    }
    __syncwarp();
    #pragma unroll
    for (int h = 0; h < 2; h++) {
        int p = 4*(lane + 32*h);
        int a = SWF(p);
        float4 vr = *(float4*)&re[a];
        float4 vi = *(float4*)&im[a];
        float t0r=vr.x,t0i=vi.x, t1r=vr.z,t1i=vi.z, t2r=vr.y,t2i=vi.y, t3r=vr.w,t3i=vi.w;
        float s0r=t0r+t2r, s0i=t0i+t2i, d0r=t0r-t2r, d0i=t0i-t2i;
        float s1r=t1r+t3r, s1i=t1i+t3i, d1r=t1r-t3r, d1i=t1i-t3i;
        float4 yr, yi;
        yr.x = s0r+s1r; yi.x = s0i+s1i;
        yr.y = d0r+d1i; yi.y = d0i-d1r;
        yr.z = s0r-s1r; yi.z = s0i-s1i;
        yr.w = d0r-d1i; yi.w = d0i+d1r;
        *(float4*)&re[a] = yr; *(float4*)&im[a] = yi;
    }
    __syncwarp();
    #pragma unroll
    for (int rq = 0; rq < 3; rq++) {
        int Q = 4 << (2*rq);
        int step = 16 >> (2*rq);
        #pragma unroll
        for (int h = 0; h < 2; h++) {
            int b = lane + 32*h;
            int j = b & (Q-1);
            int p = ((b & ~(Q-1)) << 2) + j;
            float2 w1 = tw[(j*step) & 255];
            float2 w2 = tw[(2*j*step) & 255];
            float2 w3 = tw[(3*j*step) & 255];
            int a0 = SWF(p), a1 = SWF(p+2*Q), a2 = SWF(p+Q), a3 = SWF(p+3*Q);
            float x0r=re[a0], x0i=im[a0];
            float x1r=re[a1], x1i=im[a1];
            float x2r=re[a2], x2i=im[a2];
            float x3r=re[a3], x3i=im[a3];
            float t1r = x1r*w1.x - x1i*w1.y, t1i = x1r*w1.y + x1i*w1.x;
            float t2r = x2r*w2.x - x2i*w2.y, t2i = x2r*w2.y + x2i*w2.x;
            float t3r = x3r*w3.x - x3i*w3.y, t3i = x3r*w3.y + x3i*w3.x;
            float s0r=x0r+t2r, s0i=x0i+t2i, d0r=x0r-t2r, d0i=x0i-t2i;
            float s1r=t1r+t3r, s1i=t1i+t3i, d1r=t1r-t3r, d1i=t1i-t3i;
            re[a0]=s0r+s1r; im[a0]=s0i+s1i;
            re[a2]=d0r+d1i; im[a2]=d0i-d1r;
            re[a1]=s0r-s1r; im[a1]=s0i-s1i;
            re[a3]=d0r-d1i; im[a3]=d0i+d1r;
        }
        __syncwarp();
    }
    const float SC = 0.012271846303085129f;  // 2*pi/512
    float ro[5], io[5];
    #pragma unroll
    for (int j = 0; j < 5; j++) {
        int k = lane + 32*j;
        if (k <= 128) {
            int km = (256-k) & 255;
            float zr=re[SWF(k)],  zi= im[SWF(k)];
            float mr=re[SWF(km)], mi=-im[SWF(km)];
            float er=0.5f*(zr+mr), ei=0.5f*(zi+mi);
            float dr=0.5f*(zr-mr), di=0.5f*(zi-mi);
            float pr=di, pi=-dr;
            float wr=uer[k], wi=uei[k];
            float qr=pr*wr-pi*wi, qi=pr*wi+pi*wr;
            ro[j] = (er+qr)*SC;
            io[j] = (ei+qi)*SC;
        }
    }
    __syncthreads();
    float* ore = sre;   // reuse: [129][16]
    float* oim = sim;
    #pragma unroll
    for (int j = 0; j < 5; j++) {
        int k = lane + 32*j;
        if (k <= 128) { ore[k*16+w] = ro[j]; oim[k*16+w] = io[j]; }
    }
    __syncthreads();
    int base = blockIdx.x*16;
    for (int idx = tid; idx < 129*8; idx += 512) {
        int m = idx >> 3, rr = (idx & 7) << 1;
        size_t o = (size_t)m*ROWS1 + base + rr;
        __nv_bfloat16 h0,l0,h1,l1;
        __nv_bfloat162 v;
        split2(ore[m*16+rr], h0, l0); split2(ore[m*16+rr+1], h1, l1);
        v.x=h0; v.y=h1; *(__nv_bfloat162*)&d_Xr_hi[o] = v;
        v.x=l0; v.y=l1; *(__nv_bfloat162*)&d_Xr_lo[o] = v;
        split2(oim[m*16+rr], h0, l0); split2(oim[m*16+rr+1], h1, l1);
        v.x=h0; v.y=h1; *(__nv_bfloat162*)&d_Xi_hi[o] = v;
        v.x=l0; v.y=l1; *(__nv_bfloat162*)&d_Xi_lo[o] = v;
    }
}

// ============================================================
// Stage 2b: split conv weights to bf16 hi/lo
// ============================================================
__global__ void k_wsplit(const float* __restrict__ w) {
    int i = blockIdx.x*256 + threadIdx.x;   // 65536 total
    __nv_bfloat16 h, l;
    split2(w[i], h, l);
    d_Whi[i] = h; d_Wlo[i] = l;
}

// ============================================================
// Stage 2c: At[m][klo][kh] = sum_l P[l][klo] W[l][kh] via mma.
// In-kernel fp32->bf16 hi/lo split; all K=128 resident in smem (no pipeline).
// smem: Ph(32K) Pl(32K) Wh(32K) Wl(32K); each = 4 chunks x OFF_T(32x128) tiles.
// ============================================================
__global__ void __launch_bounds__(256) k_buildA_mma(const float* __restrict__ wmat,
                                                    const float* __restrict__ pct) {
    extern __shared__ __align__(128) char dsm[];
    uint32_t sm = smem_u32(dsm);
    int tid = threadIdx.x;
    int wid = tid >> 5, lane = tid & 31;
    int wm = wid >> 1, wn = wid & 1;
    int m = blockIdx.y, kh0 = blockIdx.x * 128;

    const float* Pg = pct  + (size_t)m*LMAX*HLO;
    const float* Wg = wmat + (size_t)m*LMAX*HHI + kh0;

    // --- load + split phase: 2048 granules (l, c16) per operand ---
    #pragma unroll
    for (int p = 0; p < 8; p++) {
        int gi = p*256 + tid;
        int l = gi >> 4, c16 = gi & 15;
        uint32_t off = (uint32_t)((l >> 5) << 13) + OFF_T(l & 31, c16);
        {
            const float* sp = Pg + (size_t)l*HLO + c16*8;
            float4 v0 = *(const float4*)sp;
            float4 v1 = *(const float4*)(sp+4);
            __nv_bfloat16 h[8], lo[8];
            split2(v0.x,h[0],lo[0]); split2(v0.y,h[1],lo[1]); split2(v0.z,h[2],lo[2]); split2(v0.w,h[3],lo[3]);
            split2(v1.x,h[4],lo[4]); split2(v1.y,h[5],lo[5]); split2(v1.z,h[6],lo[6]); split2(v1.w,h[7],lo[7]);
            *(uint4*)(dsm + off)          = *(uint4*)h;
            *(uint4*)(dsm + 32768 + off)  = *(uint4*)lo;
        }
        {
            const float* sw = Wg + (size_t)l*HHI + c16*8;
            float4 v0 = *(const float4*)sw;
            float4 v1 = *(const float4*)(sw+4);
            __nv_bfloat16 h[8], lo[8];
            split2(v0.x,h[0],lo[0]); split2(v0.y,h[1],lo[1]); split2(v0.z,h[2],lo[2]); split2(v0.w,h[3],lo[3]);
            split2(v1.x,h[4],lo[4]); split2(v1.y,h[5],lo[5]); split2(v1.z,h[6],lo[6]); split2(v1.w,h[7],lo[7]);
            *(uint4*)(dsm + 65536 + off)  = *(uint4*)h;
            *(uint4*)(dsm + 98304 + off)  = *(uint4*)lo;
        }
    }
    __syncthreads();

    float acc[2][8][4];
    #pragma unroll
    for (int i=0;i<2;i++) for (int j=0;j<8;j++) for (int q=0;q<4;q++) acc[i][j][q] = 0.f;

    #pragma unroll 1
    for (int kc = 0; kc < 4; kc++) {
        uint32_t cb = (uint32_t)(kc << 13);
        uint32_t sPh = sm + cb, sPl = sm + 32768 + cb, sWh = sm + 65536 + cb, sWl = sm + 98304 + cb;

        #pragma unroll
        for (int ks = 0; ks < 2; ks++) {
            int kr = ks*16 + (lane & 7) + ((lane >> 3) & 1)*8;
            uint32_t a_h[2][4], a_l[2][4];
            #pragma unroll
            for (int mi = 0; mi < 2; mi++) {
                int mcol = wm*4 + mi*2 + ((lane >> 4) & 1);
                uint32_t off = OFF_T(kr, mcol);
                uint32_t r0,r1,r2,r3;
                ldsm_x4_t(r0, r1, r2, r3, sPh + off);
                a_h[mi][0]=r0; a_h[mi][1]=r2; a_h[mi][2]=r1; a_h[mi][3]=r3;
                ldsm_x4_t(r0, r1, r2, r3, sPl + off);
                a_l[mi][0]=r0; a_l[mi][1]=r2; a_l[mi][2]=r1; a_l[mi][3]=r3;
            }
            uint32_t b[4][4];
            #pragma unroll
            for (int nj = 0; nj < 4; nj++) {
                int n = wn*64 + nj*16 + ((lane >> 4) & 1)*8;
                uint32_t off = OFF_T(kr, (n >> 3));
                ldsm_x4_t(b[nj][0], b[nj][1], b[nj][2], b[nj][3], sWh + off);
            }
            #pragma unroll
            for (int mi = 0; mi < 2; mi++)
                #pragma unroll
                for (int nj = 0; nj < 4; nj++) {
                    mma16816(acc[mi][nj*2],   a_h[mi], b[nj][0], b[nj][1]);
                    mma16816(acc[mi][nj*2+1], a_h[mi], b[nj][2], b[nj][3]);
                }
            #pragma unroll
            for (int mi = 0; mi < 2; mi++)
                #pragma unroll
                for (int nj = 0; nj < 4; nj++) {
                    mma16816(acc[mi][nj*2],   a_l[mi], b[nj][0], b[nj][1]);
                    mma16816(acc[mi][nj*2+1], a_l[mi], b[nj][2], b[nj][3]);
                }
            #pragma unroll
            for (int nj = 0; nj < 4; nj++) {
                int n = wn*64 + nj*16 + ((lane >> 4) & 1)*8;
                uint32_t off = OFF_T(kr, (n >> 3));
                ldsm_x4_t(b[nj][0], b[nj][1], b[nj][2], b[nj][3], sWl + off);
            }
            #pragma unroll
            for (int mi = 0; mi < 2; mi++)
                #pragma unroll
                for (int nj = 0; nj < 4; nj++) {
                    mma16816(acc[mi][nj*2],   a_h[mi], b[nj][0], b[nj][1]);
                    mma16816(acc[mi][nj*2+1], a_h[mi], b[nj][2], b[nj][3]);
                }
        }
    }

    int g = lane >> 2, tg = lane & 3;
    size_t Abase = (size_t)m*(HLO*HHI);
    #pragma unroll
    for (int mi = 0; mi < 2; mi++) {
        #pragma unroll
        for (int half = 0; half < 2; half++) {
            int r = wm*32 + mi*16 + g + half*8;
            #pragma unroll
            for (int nt = 0; nt < 8; nt++) {
                int col = kh0 + wn*64 + nt*8 + tg*2;
                float v0 = acc[mi][nt][half*2], v1 = acc[mi][nt][half*2+1];
                __nv_bfloat16 h0,l0,h1,l1;
                split2(v0, h0, l0); split2(v1, h1, l1);
                __nv_bfloat162 vh; vh.x=h0; vh.y=h1;
                __nv_bfloat162 vl; vl.x=l0; vl.y=l1;
                *(__nv_bfloat162*)&d_At_hi[Abase + (size_t)r*HHI + col] = vh;
                *(__nv_bfloat162*)&d_At_lo[Abase + (size_t)r*HHI + col] = vl;
            }
        }
    }
}

// ============================================================
// Stage 3: Legendre per-m GEMM.
// ============================================================
__global__ void __launch_bounds__(256) k_legendre_mma() {
    extern __shared__ __align__(128) char dsm[];
    int m = blockIdx.y;
    int bx = blockIdx.x;
    int half = bx >> 2;
    int bc0  = (bx & 3) * 128;
    size_t xo = (size_t)m*ROWS1 + (size_t)bc0*HHI;
    const __nv_bfloat16 *Ah, *Al;
    float* D;
    if (half) { Ah = d_Xi_hi + xo; Al = d_Xi_lo + xo; D = d_Gi; }
    else      { Ah = d_Xr_hi + xo; Al = d_Xr_lo + xo; D = d_Gr; }
    D += (size_t)m*ROWS2 + (size_t)bc0*HLO;
    const __nv_bfloat16* Bh = d_At_hi + (size_t)m*(HLO*HHI);
    const __nv_bfloat16* Bl = d_At_lo + (size_t)m*(HLO*HHI);
    gemm_nn(Ah, Al, Bh, Bl, D, HLO, smem_u32(dsm));
}

// ============================================================
// Stage 4: irfft(n=256)*256 per row via packed radix-4 128-pt inverse FFT.
// 16 rows/block, 512 threads.
// ============================================================
__global__ void __launch_bounds__(512) k_ifft() {
    __shared__ float gre[129*16], gim[129*16];
    __shared__ float sre[16*144], sim[16*144];
    __shared__ float2 tw2[128];
    __shared__ float wqr[128], wqi[128];
    int tid = threadIdx.x;
    if (tid < 128){ float s,c; sincosf(6.283185307179586f*(float)tid/128.f,&s,&c); tw2[tid]=make_float2(c,s); }
    if (tid >= 128 && tid < 256){ int t = tid-128; float s,c; sincosf(6.283185307179586f*(float)t/256.f,&s,&c); wqr[t]=c; wqi[t]=s; }
    int base = blockIdx.x*16;
    for (int idx = tid; idx < 129*16; idx += 512) {
        int m = idx >> 4, r = idx & 15;
        gre[idx] = d_Gr[m*ROWS2 + base + r];
        gim[idx] = d_Gi[m*ROWS2 + base + r];
    }
    __syncthreads();
    int w = tid >> 5, lane = tid & 31;
    float* re = sre + w*144;
    float* im = sim + w*144;
    #pragma unroll 4
    for (int k = lane; k < 128; k += 32) {
        float ar = gre[k*16+w],        ai =  gim[k*16+w];
        float br = gre[(128-k)*16+w],  bi = -gim[(128-k)*16+w];
        float wr = wqr[k], wi = wqi[k];
        float c1r = 1.f - wi, c1i =  wr;
        float c2r = 1.f + wi, c2i = -wr;
        float Zr = ar*c1r - ai*c1i + br*c2r - bi*c2i;
        float Zi = ar*c1i + ai*c1r + br*c2i + bi*c2r;
        int rv = __brev(k) >> 25;
        re[SWF(rv)] = Zr; im[SWF(rv)] = Zi;
    }
    __syncwarp();
    {
        int p = 4*lane;
        int a = SWF(p);
        float4 vr = *(float4*)&re[a];
        float4 vi = *(float4*)&im[a];
        float t0r=vr.x,t0i=vi.x, t1r=vr.z,t1i=vi.z, t2r=vr.y,t2i=vi.y, t3r=vr.w,t3i=vi.w;
        float s0r=t0r+t2r, s0i=t0i+t2i, d0r=t0r-t2r, d0i=t0i-t2i;
        float s1r=t1r+t3r, s1i=t1i+t3i, d1r=t1r-t3r, d1i=t1i-t3i;
        float4 yr, yi;
        yr.x = s0r+s1r; yi.x = s0i+s1i;
        yr.y = d0r-d1i; yi.y = d0i+d1r;
        yr.z = s0r-s1r; yi.z = s0i-s1i;
        yr.w = d0r+d1i; yi.w = d0i-d1r;
        *(float4*)&re[a] = yr; *(float4*)&im[a] = yi;
    }
    __syncwarp();
    #pragma unroll
    for (int rq = 0; rq < 2; rq++) {
        int Q = 4 << (2*rq);
        int step = 8 >> (2*rq);
        int b = lane;
        int j = b & (Q-1);
        int p = ((b & ~(Q-1)) << 2) + j;
        float2 w1 = tw2[(j*step) & 127];
        float2 w2 = tw2[(2*j*step) & 127];
        float2 w3 = tw2[(3*j*step) & 127];
        int a0 = SWF(p), a1 = SWF(p+2*Q), a2 = SWF(p+Q), a3 = SWF(p+3*Q);
        float x0r=re[a0], x0i=im[a0];
        float x1r=re[a1], x1i=im[a1];
        float x2r=re[a2], x2i=im[a2];
        float x3r=re[a3], x3i=im[a3];
        float t1r = x1r*w1.x - x1i*w1.y, t1i = x1r*w1.y + x1i*w1.x;
        float t2r = x2r*w2.x - x2i*w2.y, t2i = x2r*w2.y + x2i*w2.x;
        float t3r = x3r*w3.x - x3i*w3.y, t3i = x3r*w3.y + x3i*w3.x;
        float s0r=x0r+t2r, s0i=x0i+t2i, d0r=x0r-t2r, d0i=x0i-t2i;
        float s1r=t1r+t3r, s1i=t1i+t3i, d1r=t1r-t3r, d1i=t1i-t3i;
        re[a0]=s0r+s1r; im[a0]=s0i+s1i;
        re[a2]=d0r-d1i; im[a2]=d0i+d1r;
        re[a1]=s0r-s1r; im[a1]=s0i-s1i;
        re[a3]=d0r+d1i; im[a3]=d0i-d1r;
        __syncwarp();
    }
    #pragma unroll
    for (int h = 0; h < 2; h++) {
        int p = lane + 32*h;
        float2 wv = tw2[p];
        int a0 = SWF(p), a1 = SWF(p+64);
        float x0r=re[a0], x0i=im[a0];
        float x1r=re[a1], x1i=im[a1];
        float tr = x1r*wv.x - x1i*wv.y, ti = x1r*wv.y + x1i*wv.x;
        re[a0]=x0r+tr; im[a0]=x0i+ti;
        re[a1]=x0r-tr; im[a1]=x0i-ti;
    }
    __syncwarp();
    __nv_bfloat162* yh = (__nv_bfloat162*)d_Yc_hi + (size_t)(base + w)*128;
    __nv_bfloat162* yl = (__nv_bfloat162*)d_Yc_lo + (size_t)(base + w)*128;
    #pragma unroll 4
    for (int n = lane; n < 128; n += 32) {
        __nv_bfloat16 h0,l0,h1,l1;
        split2(re[SWF(n)], h0, l0);
        split2(im[SWF(n)], h1, l1);
        __nv_bfloat162 vh; vh.x=h0; vh.y=h1;
        __nv_bfloat162 vl; vl.x=l0; vl.y=l1;
        yh[n] = vh; yl[n] = vl;
    }
}

// ============================================================
// Stage 5: 1x1 conv + fused GN partial stats.
// ============================================================
__global__ void __launch_bounds__(256) k_conv_mma(const float* __restrict__ bias) {
    extern __shared__ __align__(128) char dsm[];
    int b = blockIdx.z, o0 = blockIdx.y*128, hw0 = blockIdx.x*128;
    int blin = (b*2 + blockIdx.y)*256 + blockIdx.x;
    const __nv_bfloat16* Ah = d_Whi + (size_t)o0*CIN;
    const __nv_bfloat16* Al = d_Wlo + (size_t)o0*CIN;
    const __nv_bfloat16* Bh = d_Yc_hi + (size_t)b*CIN*HWLO + hw0;
    const __nv_bfloat16* Bl = d_Yc_lo + (size_t)b*CIN*HWLO + hw0;
    float* D = d_H + ((size_t)b*COUT + o0)*HWLO + hw0;
    gemm_kn(Ah, Al, Bh, Bl, (size_t)HWLO, D, HWLO, bias + o0, smem_u32(dsm),
            dsm, d_cps, d_cps2, blin);
}

// ============================================================
// Stage 6: GroupNorm final stats — 64 blocks, one per (b,g), parallel tree.
// ============================================================
__global__ void k_gnfin() {
    __shared__ double sh[256], sh2[256];
    int bg = blockIdx.x;               // b*32 + g
    int b = bg >> 5, g = bg & 31;
    int y = g >> 4, gi = g & 15;
    int t = threadIdx.x;               // 256 = one partial per thread
    int idx = ((b*2 + y)*256 + t)*16 + gi;
    sh[t]  = (double)d_cps [idx];
    sh2[t] = (double)d_cps2[idx];
    __syncthreads();
    for (int st = 128; st > 0; st >>= 1) {
        if (t < st) { sh[t] += sh[t+st]; sh2[t] += sh2[t+st]; }
        __syncthreads();
    }
    if (t == 0) {
        const double N = (double)(CPG*HWLO);
        double mean = sh[0] / N;
        double var  = sh2[0] / N - mean*mean;
        d_mean[bg] = (float)mean;
        d_rstd[bg] = rsqrtf((float)var + 1e-5f);
    }
}

// ============================================================
// Stage 7: normalize + affine + exact GELU
// ============================================================
__global__ void k_gnapply(const float* __restrict__ gamma, const float* __restrict__ beta,
                          float* __restrict__ out) {
    int idx = blockIdx.x*256 + threadIdx.x;
    int fidx = idx * 4;
    int o  = (fidx >> 15) & 255;
    int bg = fidx >> 18;
    float a  = gamma[o] * d_rstd[bg];
    float b2 = beta[o] - d_mean[bg] * a;
    float4 h = ((const float4*)d_H)[idx];
    float v0 = h.x*a + b2, v1 = h.y*a + b2, v2 = h.z*a + b2, v3 = h.w*a + b2;
    float4 r;
    r.x = v0 * normcdff(v0);
    r.y = v1 * normcdff(v1);
    r.z = v2 * normcdff(v2);
    r.w = v3 * normcdff(v3);
    ((float4*)out)[idx] = r;
}

// ============================================================
extern "C" void kernel_launch(void* const* d_in, const int* in_sizes, int n_in,
                              void* d_out, int out_size) {
    const float* x      = (const float*)d_in[0];
    const float* conv_w = (const float*)d_in[1];
    const float* conv_b = (const float*)d_in[2];
    const float* gamma  = (const float*)d_in[3];
    const float* beta   = (const float*)d_in[4];
    const float* wmat   = (const float*)d_in[5];
    const float* pct    = (const float*)d_in[6];
    float* out = (float*)d_out;

    cudaFuncSetAttribute(k_buildA_mma,   cudaFuncAttributeMaxDynamicSharedMemorySize, BA_SMEM);
    cudaFuncSetAttribute(k_legendre_mma, cudaFuncAttributeMaxDynamicSharedMemorySize, GEMM_SMEM);
    cudaFuncSetAttribute(k_conv_mma,     cudaFuncAttributeMaxDynamicSharedMemorySize, GEMM_SMEM);

    k_fft_fwd     <<<ROWS1/16, 512>>>(x);
    k_wsplit      <<<256, 256>>>(conv_w);
    k_buildA_mma  <<<dim3(2, MMAX), 256, BA_SMEM>>>(wmat, pct);
    k_legendre_mma<<<dim3(8, MMAX), 256, GEMM_SMEM>>>();
    k_ifft        <<<ROWS2/16, 512>>>();
    k_conv_mma    <<<dim3(HWLO/128, COUT/128, BATCH), 256, GEMM_SMEM>>>(conv_b);
    k_gnfin       <<<64, 256>>>();
    k_gnapply     <<<(BC*HWLO)/4/256, 256>>>(gamma, beta, out);
}